// round 1
// baseline (speedup 1.0000x reference)
#include <cuda_runtime.h>
#include <math.h>

#define S_LEN 2048
#define H_DIM 1024
#define NHEAD 16
#define KVHEAD 8
#define HDIM 64
#define NEXP 8
#define IDIM 3584

// ---------------- scratch (static device globals; zero-init at load) ----------
__device__ float g_xn[S_LEN * H_DIM];
__device__ float g_q[S_LEN * NHEAD * HDIM];
__device__ float g_k[S_LEN * KVHEAD * HDIM];
__device__ float g_v[S_LEN * KVHEAD * HDIM];
__device__ float g_ctx[S_LEN * NHEAD * HDIM];
__device__ float g_hid[S_LEN * H_DIM];
__device__ int   g_cnt[NEXP];
__device__ int   g_tok[NEXP * S_LEN];
__device__ float g_twgt[NEXP * S_LEN];
__device__ float g_s1[(size_t)NEXP * S_LEN * IDIM];
__device__ float g_s3[(size_t)NEXP * S_LEN * IDIM];

// ---------------- reset ----------------
__global__ void reset_kernel() {
    if (threadIdx.x < NEXP) g_cnt[threadIdx.x] = 0;
}

// ---------------- rmsnorm ----------------
__global__ void rmsnorm_kernel(const float* __restrict__ x,
                               const float* __restrict__ w,
                               float* __restrict__ o) {
    int row = blockIdx.x;
    const float* xr = x + (size_t)row * H_DIM;
    float s = 0.f;
    for (int i = threadIdx.x; i < H_DIM; i += 256) {
        float v = xr[i];
        s += v * v;
    }
    __shared__ float red[8];
    int lane = threadIdx.x & 31, wid = threadIdx.x >> 5;
    #pragma unroll
    for (int off = 16; off; off >>= 1) s += __shfl_xor_sync(0xffffffffu, s, off);
    if (lane == 0) red[wid] = s;
    __syncthreads();
    if (wid == 0) {
        float t = (lane < 8) ? red[lane] : 0.f;
        #pragma unroll
        for (int off = 4; off; off >>= 1) t += __shfl_xor_sync(0xffffffffu, t, off);
        if (lane == 0) red[0] = t;
    }
    __syncthreads();
    float inv = rsqrtf(red[0] * (1.f / H_DIM) + 1e-6f);
    for (int i = threadIdx.x; i < H_DIM; i += 256)
        o[(size_t)row * H_DIM + i] = w[i] * xr[i] * inv;
}

// ---------------- generic NT GEMM: C[M,N] = A[M,K] @ B[N,K]^T ----------------
// MODE 0: plain store
// MODE 1: C = acc + resid; also stores identical values to out2
// MODE 2: per-expert (z): gathered A rows (token ids), early-exit on count
// MODE 3: per-expert (z): A = h slots, epilogue atomicAdd(finalout[token], w*acc)
template <int MODE>
__global__ void gemm_nt(const float* __restrict__ A,
                        const float* __restrict__ Bb,
                        float* __restrict__ Cb,
                        int M, int N, int K,
                        const float* __restrict__ resid,
                        float* __restrict__ out2,
                        float* __restrict__ finalout) {
    int z = blockIdx.z;
    int cnt = M;
    const int* idx = nullptr;
    const float* wgt = nullptr;
    const float* B = Bb;
    float* C = Cb;
    if (MODE == 2) {
        cnt = g_cnt[z];
        if ((int)blockIdx.y * 128 >= cnt) return;
        idx = g_tok + z * S_LEN;
        B = Bb + (size_t)z * IDIM * H_DIM;
        C = Cb + (size_t)z * S_LEN * IDIM;
    }
    if (MODE == 3) {
        cnt = g_cnt[z];
        if ((int)blockIdx.y * 128 >= cnt) return;
        idx = g_tok + z * S_LEN;
        wgt = g_twgt + z * S_LEN;
        A = A + (size_t)z * S_LEN * IDIM;
        B = Bb + (size_t)z * H_DIM * IDIM;
    }

    __shared__ float As[8][132];
    __shared__ float Bs[8][132];

    int tid = threadIdx.x;
    int tx = tid & 15, ty = tid >> 4;
    int m0 = blockIdx.y * 128;
    int n0 = blockIdx.x * 128;

    int lrow = tid >> 1;
    int lk = (tid & 1) * 4;

    int arow;
    if (MODE == 2) {
        int m = m0 + lrow;
        arow = (m < cnt) ? idx[m] : 0;
    } else {
        arow = m0 + lrow;
    }
    const float* Aptr = A + (size_t)arow * K + lk;
    const float* Bptr = B + (size_t)(n0 + lrow) * K + lk;

    float acc[8][8];
    #pragma unroll
    for (int i = 0; i < 8; i++)
        #pragma unroll
        for (int j = 0; j < 8; j++) acc[i][j] = 0.f;

    for (int k0 = 0; k0 < K; k0 += 8) {
        float4 av = *(const float4*)(Aptr + k0);
        float4 bv = *(const float4*)(Bptr + k0);
        As[lk + 0][lrow] = av.x; As[lk + 1][lrow] = av.y;
        As[lk + 2][lrow] = av.z; As[lk + 3][lrow] = av.w;
        Bs[lk + 0][lrow] = bv.x; Bs[lk + 1][lrow] = bv.y;
        Bs[lk + 2][lrow] = bv.z; Bs[lk + 3][lrow] = bv.w;
        __syncthreads();
        #pragma unroll
        for (int kk = 0; kk < 8; kk++) {
            float a[8], b[8];
            #pragma unroll
            for (int i = 0; i < 8; i++) a[i] = As[kk][ty * 8 + i];
            #pragma unroll
            for (int j = 0; j < 8; j++) b[j] = Bs[kk][tx * 8 + j];
            #pragma unroll
            for (int i = 0; i < 8; i++)
                #pragma unroll
                for (int j = 0; j < 8; j++) acc[i][j] += a[i] * b[j];
        }
        __syncthreads();
    }

    #pragma unroll
    for (int i = 0; i < 8; i++) {
        int m = m0 + ty * 8 + i;
        if ((MODE == 2 || MODE == 3) && m >= cnt) continue;
        int n = n0 + tx * 8;
        if (MODE == 0) {
            float4 v0 = make_float4(acc[i][0], acc[i][1], acc[i][2], acc[i][3]);
            float4 v1 = make_float4(acc[i][4], acc[i][5], acc[i][6], acc[i][7]);
            *(float4*)(C + (size_t)m * N + n) = v0;
            *(float4*)(C + (size_t)m * N + n + 4) = v1;
        } else if (MODE == 1) {
            size_t o = (size_t)m * N + n;
            float4 r0 = *(const float4*)(resid + o);
            float4 r1 = *(const float4*)(resid + o + 4);
            float4 v0 = make_float4(acc[i][0] + r0.x, acc[i][1] + r0.y,
                                    acc[i][2] + r0.z, acc[i][3] + r0.w);
            float4 v1 = make_float4(acc[i][4] + r1.x, acc[i][5] + r1.y,
                                    acc[i][6] + r1.z, acc[i][7] + r1.w);
            *(float4*)(C + o) = v0; *(float4*)(C + o + 4) = v1;
            *(float4*)(out2 + o) = v0; *(float4*)(out2 + o + 4) = v1;
        } else if (MODE == 2) {
            float4 v0 = make_float4(acc[i][0], acc[i][1], acc[i][2], acc[i][3]);
            float4 v1 = make_float4(acc[i][4], acc[i][5], acc[i][6], acc[i][7]);
            *(float4*)(C + (size_t)m * N + n) = v0;
            *(float4*)(C + (size_t)m * N + n + 4) = v1;
        } else {  // MODE 3
            float w = wgt[m];
            float* dst = finalout + (size_t)idx[m] * N + n;
            #pragma unroll
            for (int j = 0; j < 8; j++) atomicAdd(dst + j, w * acc[i][j]);
        }
    }
}

// ---------------- RoPE (in place on q,k) ----------------
__global__ void rope_kernel(float* __restrict__ q, float* __restrict__ k) {
    int s = blockIdx.x, h = blockIdx.y, d = threadIdx.x;  // d in [0,32)
    float inv_freq = powf(1000000.0f, -(float)(2 * d) / 64.0f);
    float ang = (float)s * inv_freq;
    float sn, c;
    sincosf(ang, &sn, &c);
    float* base = (h < NHEAD) ? (q + ((size_t)s * NHEAD + h) * HDIM)
                              : (k + ((size_t)s * KVHEAD + (h - NHEAD)) * HDIM);
    float x1 = base[d], x2 = base[d + 32];
    base[d]      = x1 * c - x2 * sn;
    base[d + 32] = x2 * c + x1 * sn;
}

// ---------------- flash attention (causal, GQA) ----------------
// grid: (S/64 query tiles, NHEAD), block 256, dynamic smem 4*64*65 floats
__global__ void attn_kernel(const float* __restrict__ q,
                            const float* __restrict__ k,
                            const float* __restrict__ v,
                            float* __restrict__ ctx) {
    extern __shared__ float sm[];
    float* Qs = sm;                 // [64][65]
    float* Ks = Qs + 64 * 65;
    float* Vs = Ks + 64 * 65;
    float* Ps = Vs + 64 * 65;

    int qt = blockIdx.x, h = blockIdx.y;
    int kvh = h >> 1;
    int tid = threadIdx.x;
    int r = tid >> 2;       // query row in tile
    int cg = tid & 3;       // col group (16 cols each)
    int d0 = cg * 16;

    for (int i = tid; i < 64 * 64; i += 256) {
        int rr = i >> 6, dd = i & 63;
        Qs[rr * 65 + dd] = q[((size_t)(qt * 64 + rr) * NHEAD + h) * HDIM + dd] * 0.125f;
    }

    float m = -1e30f, l = 0.f;
    float o[16];
    #pragma unroll
    for (int j = 0; j < 16; j++) o[j] = 0.f;
    int qrow_g = qt * 64 + r;

    for (int kt = 0; kt <= qt; kt++) {
        for (int i = tid; i < 64 * 64; i += 256) {
            int rr = i >> 6, dd = i & 63;
            size_t off = ((size_t)(kt * 64 + rr) * KVHEAD + kvh) * HDIM + dd;
            Ks[rr * 65 + dd] = k[off];
            Vs[rr * 65 + dd] = v[off];
        }
        __syncthreads();

        float sc[16];
        #pragma unroll
        for (int j = 0; j < 16; j++) sc[j] = 0.f;
        for (int kk = 0; kk < 64; kk++) {
            float a = Qs[r * 65 + kk];
            #pragma unroll
            for (int j = 0; j < 16; j++) sc[j] += a * Ks[(d0 + j) * 65 + kk];
        }
        float tmax = -1e30f;
        #pragma unroll
        for (int j = 0; j < 16; j++) {
            int cglob = kt * 64 + d0 + j;
            if (cglob > qrow_g) sc[j] = -1e30f;
            tmax = fmaxf(tmax, sc[j]);
        }
        tmax = fmaxf(tmax, __shfl_xor_sync(0xffffffffu, tmax, 1));
        tmax = fmaxf(tmax, __shfl_xor_sync(0xffffffffu, tmax, 2));
        float mnew = fmaxf(m, tmax);
        float alpha = __expf(m - mnew);
        float lsum = 0.f;
        #pragma unroll
        for (int j = 0; j < 16; j++) {
            float p = __expf(sc[j] - mnew);
            Ps[r * 65 + d0 + j] = p;
            lsum += p;
        }
        lsum += __shfl_xor_sync(0xffffffffu, lsum, 1);
        lsum += __shfl_xor_sync(0xffffffffu, lsum, 2);
        l = l * alpha + lsum;
        m = mnew;
        #pragma unroll
        for (int j = 0; j < 16; j++) o[j] *= alpha;
        __syncthreads();

        for (int c = 0; c < 64; c++) {
            float p = Ps[r * 65 + c];
            #pragma unroll
            for (int j = 0; j < 16; j++) o[j] += p * Vs[c * 65 + d0 + j];
        }
        __syncthreads();
    }

    float invl = 1.f / l;
    #pragma unroll
    for (int j = 0; j < 16; j++)
        ctx[((size_t)qrow_g * NHEAD + h) * HDIM + d0 + j] = o[j] * invl;
}

// ---------------- router: gate GEMV + softmax + top-2 (pairwise argmax) ------
__global__ void router_kernel(const float* __restrict__ xn,
                              const float* __restrict__ gw) {
    int t = blockIdx.x;
    int wid = threadIdx.x >> 5, lane = threadIdx.x & 31;
    __shared__ float logit[NEXP];
    const float* xr = xn + (size_t)t * H_DIM;
    const float* gr = gw + (size_t)wid * H_DIM;
    float s = 0.f;
    for (int i = lane; i < H_DIM; i += 32) s += xr[i] * gr[i];
    #pragma unroll
    for (int off = 16; off; off >>= 1) s += __shfl_xor_sync(0xffffffffu, s, off);
    if (lane == 0) logit[wid] = s;
    __syncthreads();
    if (threadIdx.x == 0) {
        float mx = -1e30f;
        for (int e = 0; e < NEXP; e++) mx = fmaxf(mx, logit[e]);
        float rw[NEXP], sum = 0.f;
        for (int e = 0; e < NEXP; e++) { rw[e] = expf(logit[e] - mx); sum += rw[e]; }
        float invs = 1.f / sum;
        for (int e = 0; e < NEXP; e++) rw[e] *= invs;
        int ba = 0, bb = 1;
        float best = -1.f;
        for (int a = 0; a < NEXP; a++)
            for (int b = a + 1; b < NEXP; b++) {
                float vv = rw[a] + rw[b];
                if (vv > best) { best = vv; ba = a; bb = b; }
            }
        float wa = rw[ba], wb = rw[bb];
        float inv = 1.f / (wa + wb);
        int sa = atomicAdd(&g_cnt[ba], 1);
        g_tok[ba * S_LEN + sa] = t; g_twgt[ba * S_LEN + sa] = wa * inv;
        int sb = atomicAdd(&g_cnt[bb], 1);
        g_tok[bb * S_LEN + sb] = t; g_twgt[bb * S_LEN + sb] = wb * inv;
    }
}

// ---------------- silu(s1) * s3 -> s1 (per valid slot row) ----------------
__global__ void silu_mul_kernel() {
    int e = blockIdx.z;
    int row = blockIdx.y;
    if (row >= g_cnt[e]) return;
    size_t off = ((size_t)e * S_LEN + row) * IDIM + blockIdx.x * 256 + threadIdx.x;
    float a = g_s1[off], b = g_s3[off];
    g_s1[off] = a * (1.f / (1.f + expf(-a))) * b;
}

// ---------------- launch ----------------
static void* symaddr(const void* sym) {
    void* p = nullptr;
    cudaGetSymbolAddress(&p, sym);
    return p;
}

extern "C" void kernel_launch(void* const* d_in, const int* in_sizes, int n_in,
                              void* d_out, int out_size) {
    const float* hidden = (const float*)d_in[0];
    const float* ln1    = (const float*)d_in[1];
    const float* ln2    = (const float*)d_in[2];
    const float* wq     = (const float*)d_in[3];
    const float* wk     = (const float*)d_in[4];
    const float* wv     = (const float*)d_in[5];
    const float* wo     = (const float*)d_in[6];
    const float* gate   = (const float*)d_in[7];
    const float* w1     = (const float*)d_in[8];
    const float* w2     = (const float*)d_in[9];
    const float* w3     = (const float*)d_in[10];
    float* out = (float*)d_out;

    float* xn  = (float*)symaddr(g_xn);
    float* q   = (float*)symaddr(g_q);
    float* k   = (float*)symaddr(g_k);
    float* v   = (float*)symaddr(g_v);
    float* ctx = (float*)symaddr(g_ctx);
    float* hid = (float*)symaddr(g_hid);
    float* s1  = (float*)symaddr(g_s1);
    float* s3  = (float*)symaddr(g_s3);

    reset_kernel<<<1, 32>>>();
    rmsnorm_kernel<<<S_LEN, 256>>>(hidden, ln1, xn);

    gemm_nt<0><<<dim3(8, 16, 1), 256>>>(xn, wq, q, S_LEN, NHEAD * HDIM, H_DIM,
                                        nullptr, nullptr, nullptr);
    gemm_nt<0><<<dim3(4, 16, 1), 256>>>(xn, wk, k, S_LEN, KVHEAD * HDIM, H_DIM,
                                        nullptr, nullptr, nullptr);
    gemm_nt<0><<<dim3(4, 16, 1), 256>>>(xn, wv, v, S_LEN, KVHEAD * HDIM, H_DIM,
                                        nullptr, nullptr, nullptr);

    rope_kernel<<<dim3(S_LEN, NHEAD + KVHEAD), 32>>>(q, k);

    int attn_smem = 4 * 64 * 65 * sizeof(float);
    cudaFuncSetAttribute(attn_kernel, cudaFuncAttributeMaxDynamicSharedMemorySize,
                         attn_smem);
    attn_kernel<<<dim3(S_LEN / 64, NHEAD), 256, attn_smem>>>(q, k, v, ctx);

    gemm_nt<1><<<dim3(8, 16, 1), 256>>>(ctx, wo, hid, S_LEN, H_DIM, NHEAD * HDIM,
                                        hidden, out, nullptr);

    rmsnorm_kernel<<<S_LEN, 256>>>(hid, ln2, xn);
    router_kernel<<<S_LEN, 256>>>(xn, gate);

    gemm_nt<2><<<dim3(IDIM / 128, S_LEN / 128, NEXP), 256>>>(
        xn, w1, s1, S_LEN, IDIM, H_DIM, nullptr, nullptr, nullptr);
    gemm_nt<2><<<dim3(IDIM / 128, S_LEN / 128, NEXP), 256>>>(
        xn, w3, s3, S_LEN, IDIM, H_DIM, nullptr, nullptr, nullptr);

    silu_mul_kernel<<<dim3(IDIM / 256, S_LEN, NEXP), 256>>>();

    gemm_nt<3><<<dim3(H_DIM / 128, S_LEN / 128, NEXP), 256>>>(
        s1, w2, nullptr, S_LEN, H_DIM, IDIM, nullptr, nullptr, out);
}

// round 4
// speedup vs baseline: 1.1153x; 1.1153x over previous
#include <cuda_runtime.h>
#include <cuda_bf16.h>
#include <math.h>
#include <stdint.h>

#define S_LEN 2048
#define H_DIM 1024
#define NHEAD 16
#define KVHEAD 8
#define HDIM 64
#define NEXP 8
#define IDIM 3584
#define QKV_LD 2048

typedef __nv_bfloat16 bf16;

// ---------------- scratch ----------------
__device__ float g_xn[S_LEN * H_DIM];
__device__ __align__(16) bf16 g_xnh[S_LEN * H_DIM];
__device__ __align__(16) bf16 g_xnl[S_LEN * H_DIM];
__device__ float g_qkv[S_LEN * QKV_LD];
__device__ float g_ctx[S_LEN * H_DIM];
__device__ __align__(16) bf16 g_ctxh[S_LEN * H_DIM];
__device__ __align__(16) bf16 g_ctxl[S_LEN * H_DIM];
__device__ float g_hid[S_LEN * H_DIM];
__device__ int   g_cnt[NEXP];
__device__ int   g_tok[NEXP * S_LEN];
__device__ float g_twgt[NEXP * S_LEN];
__device__ float g_s1[(size_t)NEXP * S_LEN * IDIM];
__device__ float g_s3[(size_t)NEXP * S_LEN * IDIM];
__device__ __align__(16) bf16 g_s1h[(size_t)NEXP * S_LEN * IDIM];
__device__ __align__(16) bf16 g_s1l[(size_t)NEXP * S_LEN * IDIM];
__device__ __align__(16) bf16 g_wqkvh[QKV_LD * H_DIM];
__device__ __align__(16) bf16 g_wqkvl[QKV_LD * H_DIM];
__device__ __align__(16) bf16 g_woh[H_DIM * NHEAD * HDIM];
__device__ __align__(16) bf16 g_wol[H_DIM * NHEAD * HDIM];
__device__ __align__(16) bf16 g_w1h[(size_t)NEXP * IDIM * H_DIM];
__device__ __align__(16) bf16 g_w1l[(size_t)NEXP * IDIM * H_DIM];
__device__ __align__(16) bf16 g_w2h[(size_t)NEXP * H_DIM * IDIM];
__device__ __align__(16) bf16 g_w2l[(size_t)NEXP * H_DIM * IDIM];
__device__ __align__(16) bf16 g_w3h[(size_t)NEXP * IDIM * H_DIM];
__device__ __align__(16) bf16 g_w3l[(size_t)NEXP * IDIM * H_DIM];

// ---------------- ptx helpers (sm_80-level, family-target safe) ----------------
__device__ __forceinline__ uint32_t smem_u32(const void* p) {
    uint32_t a;
    asm("{ .reg .u64 t; cvta.to.shared.u64 t, %1; cvt.u32.u64 %0, t; }"
        : "=r"(a) : "l"(p));
    return a;
}

__device__ __forceinline__ void cp16(uint32_t dst, const void* src) {
    asm volatile("cp.async.cg.shared.global [%0], [%1], 16;"
                 :: "r"(dst), "l"(src) : "memory");
}
__device__ __forceinline__ void cp_commit() {
    asm volatile("cp.async.commit_group;" ::: "memory");
}
template <int N>
__device__ __forceinline__ void cp_wait() {
    asm volatile("cp.async.wait_group %0;" :: "n"(N) : "memory");
}

__device__ __forceinline__ void ldsm4(uint32_t& r0, uint32_t& r1, uint32_t& r2,
                                      uint32_t& r3, uint32_t a) {
    asm volatile("ldmatrix.sync.aligned.m8n8.x4.shared.b16 {%0,%1,%2,%3}, [%4];"
                 : "=r"(r0), "=r"(r1), "=r"(r2), "=r"(r3) : "r"(a));
}
__device__ __forceinline__ void ldsm2(uint32_t& r0, uint32_t& r1, uint32_t a) {
    asm volatile("ldmatrix.sync.aligned.m8n8.x2.shared.b16 {%0,%1}, [%2];"
                 : "=r"(r0), "=r"(r1) : "r"(a));
}

__device__ __forceinline__ void mma_bf16(float& d0, float& d1, float& d2, float& d3,
                                         uint32_t a0, uint32_t a1, uint32_t a2,
                                         uint32_t a3, uint32_t b0, uint32_t b1) {
    asm volatile(
        "mma.sync.aligned.m16n8k16.row.col.f32.bf16.bf16.f32 "
        "{%0,%1,%2,%3}, {%4,%5,%6,%7}, {%8,%9}, {%0,%1,%2,%3};"
        : "+f"(d0), "+f"(d1), "+f"(d2), "+f"(d3)
        : "r"(a0), "r"(a1), "r"(a2), "r"(a3), "r"(b0), "r"(b1));
}

__device__ __forceinline__ uint32_t pack_bf2(bf16 a, bf16 b) {
    __nv_bfloat162 t;
    t.x = a; t.y = b;
    return *reinterpret_cast<uint32_t*>(&t);
}

// ---------------- reset ----------------
__global__ void reset_kernel() {
    if (threadIdx.x < NEXP) g_cnt[threadIdx.x] = 0;
}

// ---------------- fp32 -> bf16 hi/lo split (vectorized) ----------------
__global__ void conv_split4(const float4* __restrict__ s, uint2* __restrict__ hi,
                            uint2* __restrict__ lo, int n4) {
    for (int i = blockIdx.x * blockDim.x + threadIdx.x; i < n4;
         i += gridDim.x * blockDim.x) {
        float4 v = s[i];
        bf16 h0 = __float2bfloat16(v.x), h1 = __float2bfloat16(v.y);
        bf16 h2 = __float2bfloat16(v.z), h3 = __float2bfloat16(v.w);
        bf16 l0 = __float2bfloat16(v.x - __bfloat162float(h0));
        bf16 l1 = __float2bfloat16(v.y - __bfloat162float(h1));
        bf16 l2 = __float2bfloat16(v.z - __bfloat162float(h2));
        bf16 l3 = __float2bfloat16(v.w - __bfloat162float(h3));
        uint2 H = make_uint2(pack_bf2(h0, h1), pack_bf2(h2, h3));
        uint2 L = make_uint2(pack_bf2(l0, l1), pack_bf2(l2, l3));
        hi[i] = H;
        lo[i] = L;
    }
}

// ---------------- rmsnorm (writes fp32 + bf16 hi/lo) ----------------
__global__ void rmsnorm_kernel(const float* __restrict__ x,
                               const float* __restrict__ w,
                               float* __restrict__ o,
                               bf16* __restrict__ oh, bf16* __restrict__ ol) {
    int row = blockIdx.x;
    const float* xr = x + (size_t)row * H_DIM;
    float s = 0.f;
    for (int i = threadIdx.x; i < H_DIM; i += 256) {
        float v = xr[i];
        s += v * v;
    }
    __shared__ float red[8];
    int lane = threadIdx.x & 31, wid = threadIdx.x >> 5;
    #pragma unroll
    for (int off = 16; off; off >>= 1) s += __shfl_xor_sync(0xffffffffu, s, off);
    if (lane == 0) red[wid] = s;
    __syncthreads();
    if (wid == 0) {
        float t = (lane < 8) ? red[lane] : 0.f;
        #pragma unroll
        for (int off = 4; off; off >>= 1) t += __shfl_xor_sync(0xffffffffu, t, off);
        if (lane == 0) red[0] = t;
    }
    __syncthreads();
    float inv = rsqrtf(red[0] * (1.f / H_DIM) + 1e-6f);
    for (int i = threadIdx.x; i < H_DIM; i += 256) {
        float val = w[i] * xr[i] * inv;
        size_t off = (size_t)row * H_DIM + i;
        o[off] = val;
        bf16 h = __float2bfloat16(val);
        oh[off] = h;
        ol[off] = __float2bfloat16(val - __bfloat162float(h));
    }
}

// ---------------- tensor-core NT GEMM via mma.sync ----------------
// C[M,N] = A[M,K] @ B[N,K]^T, bf16-split 3-term, fp32 accum.
// tile 128x128, BK=32, 256 threads (8 warps, warp tile 64x32), cp.async 2-stage.
// MODE 0: plain store  MODE 1: +resid, dual store  MODE 2: gather rows
// MODE 3: weighted atomic scatter
#define STG_BYTES 40960u
#define TILE_OFF 1024u

template <int MODE>
__global__ void __launch_bounds__(256) tgemm(
    const bf16* __restrict__ Ah, const bf16* __restrict__ Al,
    const bf16* __restrict__ Bhb, const bf16* __restrict__ Blb,
    float* __restrict__ Cb, int M, int N, int K,
    const float* __restrict__ resid, float* __restrict__ out2,
    float* __restrict__ finalout) {
    int z = blockIdx.z;
    int cnt = M;
    const bf16* Bh = Bhb;
    const bf16* Bl = Blb;
    float* C = Cb;
    if (MODE == 2) {
        cnt = g_cnt[z];
        if ((int)blockIdx.y * 128 >= cnt) return;
        Bh = Bhb + (size_t)z * IDIM * H_DIM;
        Bl = Blb + (size_t)z * IDIM * H_DIM;
        C = Cb + (size_t)z * S_LEN * IDIM;
    }
    if (MODE == 3) {
        cnt = g_cnt[z];
        if ((int)blockIdx.y * 128 >= cnt) return;
        Ah = Ah + (size_t)z * S_LEN * IDIM;
        Al = Al + (size_t)z * S_LEN * IDIM;
        Bh = Bhb + (size_t)z * H_DIM * IDIM;
        Bl = Blb + (size_t)z * H_DIM * IDIM;
    }

    extern __shared__ char smem[];
    uint32_t sb = smem_u32(smem);
    int* sidx = (int*)smem;
    float* swgt = (float*)(smem + 512);
    uint32_t tb = sb + TILE_OFF;

    int tid = threadIdx.x;
    int lane = tid & 31, wid = tid >> 5;
    int wr = wid >> 2, wc = wid & 3;
    int m0 = blockIdx.y * 128, n0 = blockIdx.x * 128;

    if (MODE == 2 || MODE == 3) {
        if (tid < 128) {
            int m = m0 + tid;
            sidx[tid] = (m < cnt) ? g_tok[z * S_LEN + m] : 0;
            swgt[tid] = (m < cnt) ? g_twgt[z * S_LEN + m] : 0.f;
        }
        __syncthreads();
    }

    // per-thread copy geometry: two rows (r0, r0+64), one 16B chunk each buffer
    int crow = tid >> 2;       // 0..63
    int cch = tid & 3;         // 0..3 (16B chunks along K)
    int arow0, arow1;
    if (MODE == 2) {
        arow0 = sidx[crow];
        arow1 = sidx[crow + 64];
    } else {
        arow0 = m0 + crow;
        arow1 = m0 + crow + 64;
    }
    const bf16* pAh0 = Ah + (size_t)arow0 * K + cch * 8;
    const bf16* pAl0 = Al + (size_t)arow0 * K + cch * 8;
    const bf16* pAh1 = Ah + (size_t)arow1 * K + cch * 8;
    const bf16* pAl1 = Al + (size_t)arow1 * K + cch * 8;
    const bf16* pBh0 = Bh + (size_t)(n0 + crow) * K + cch * 8;
    const bf16* pBl0 = Bl + (size_t)(n0 + crow) * K + cch * 8;
    const bf16* pBh1 = Bh + (size_t)(n0 + crow + 64) * K + cch * 8;
    const bf16* pBl1 = Bl + (size_t)(n0 + crow + 64) * K + cch * 8;
    uint32_t d0 = (uint32_t)crow * 80u + (uint32_t)cch * 16u;
    uint32_t d1 = d0 + 64u * 80u;

    float acc[4][4][4];
    #pragma unroll
    for (int a = 0; a < 4; a++)
        #pragma unroll
        for (int b = 0; b < 4; b++)
            #pragma unroll
            for (int c = 0; c < 4; c++) acc[a][b][c] = 0.f;

    int nst = K / 32;

    // issue stage 0
    {
        uint32_t st = tb;
        cp16(st + d0, pAh0);
        cp16(st + d0 + 10240u, pAl0);
        cp16(st + d1, pAh1);
        cp16(st + d1 + 10240u, pAl1);
        cp16(st + 20480u + d0, pBh0);
        cp16(st + 20480u + d0 + 10240u, pBl0);
        cp16(st + 20480u + d1, pBh1);
        cp16(st + 20480u + d1 + 10240u, pBl1);
        cp_commit();
    }

    for (int s = 0; s < nst; s++) {
        if (s + 1 < nst) {
            uint32_t st = tb + (uint32_t)((s + 1) & 1) * STG_BYTES;
            size_t ko = (size_t)(s + 1) * 32;
            cp16(st + d0, pAh0 + ko);
            cp16(st + d0 + 10240u, pAl0 + ko);
            cp16(st + d1, pAh1 + ko);
            cp16(st + d1 + 10240u, pAl1 + ko);
            cp16(st + 20480u + d0, pBh0 + ko);
            cp16(st + 20480u + d0 + 10240u, pBl0 + ko);
            cp16(st + 20480u + d1, pBh1 + ko);
            cp16(st + 20480u + d1 + 10240u, pBl1 + ko);
            cp_commit();
            cp_wait<1>();
        } else {
            cp_wait<0>();
        }
        __syncthreads();

        uint32_t st = tb + (uint32_t)(s & 1) * STG_BYTES;
        #pragma unroll
        for (int kk = 0; kk < 2; kk++) {
            uint32_t bh[4][2], bl[4][2];
            uint32_t bbase = st + 20480u +
                             (uint32_t)(wc * 32 + (lane & 7)) * 80u +
                             (uint32_t)(kk * 32 + ((lane >> 3) & 1) * 16);
            #pragma unroll
            for (int nf = 0; nf < 4; nf++) {
                ldsm2(bh[nf][0], bh[nf][1], bbase + nf * 8 * 80u);
                ldsm2(bl[nf][0], bl[nf][1], bbase + nf * 8 * 80u + 10240u);
            }
            uint32_t abase = st + (uint32_t)(wr * 64 + (lane & 15)) * 80u +
                             (uint32_t)(kk * 32 + (lane >> 4) * 16);
            #pragma unroll
            for (int mf = 0; mf < 4; mf++) {
                uint32_t ah[4], al[4];
                ldsm4(ah[0], ah[1], ah[2], ah[3], abase + mf * 16 * 80u);
                ldsm4(al[0], al[1], al[2], al[3], abase + mf * 16 * 80u + 10240u);
                #pragma unroll
                for (int nf = 0; nf < 4; nf++) {
                    mma_bf16(acc[mf][nf][0], acc[mf][nf][1], acc[mf][nf][2],
                             acc[mf][nf][3], ah[0], ah[1], ah[2], ah[3],
                             bh[nf][0], bh[nf][1]);
                    mma_bf16(acc[mf][nf][0], acc[mf][nf][1], acc[mf][nf][2],
                             acc[mf][nf][3], ah[0], ah[1], ah[2], ah[3],
                             bl[nf][0], bl[nf][1]);
                    mma_bf16(acc[mf][nf][0], acc[mf][nf][1], acc[mf][nf][2],
                             acc[mf][nf][3], al[0], al[1], al[2], al[3],
                             bh[nf][0], bh[nf][1]);
                }
            }
        }
        __syncthreads();
    }

    // epilogue
    int g = lane >> 2, cpr = (lane & 3) * 2;
    #pragma unroll
    for (int mf = 0; mf < 4; mf++) {
        int r0g = wr * 64 + mf * 16 + g;
        int m_lo = m0 + r0g, m_hi = m_lo + 8;
        #pragma unroll
        for (int nf = 0; nf < 4; nf++) {
            int n = n0 + wc * 32 + nf * 8 + cpr;
            float2 v01 = make_float2(acc[mf][nf][0], acc[mf][nf][1]);
            float2 v23 = make_float2(acc[mf][nf][2], acc[mf][nf][3]);
            if (MODE == 0) {
                *(float2*)(C + (size_t)m_lo * N + n) = v01;
                *(float2*)(C + (size_t)m_hi * N + n) = v23;
            } else if (MODE == 1) {
                size_t o_lo = (size_t)m_lo * N + n;
                size_t o_hi = (size_t)m_hi * N + n;
                float2 r0 = *(const float2*)(resid + o_lo);
                float2 r1 = *(const float2*)(resid + o_hi);
                v01.x += r0.x; v01.y += r0.y;
                v23.x += r1.x; v23.y += r1.y;
                *(float2*)(C + o_lo) = v01;
                *(float2*)(out2 + o_lo) = v01;
                *(float2*)(C + o_hi) = v23;
                *(float2*)(out2 + o_hi) = v23;
            } else if (MODE == 2) {
                if (m_lo < cnt) *(float2*)(C + (size_t)m_lo * N + n) = v01;
                if (m_hi < cnt) *(float2*)(C + (size_t)m_hi * N + n) = v23;
            } else {
                if (m_lo < cnt) {
                    float w = swgt[r0g];
                    float* dst = finalout + (size_t)sidx[r0g] * N + n;
                    atomicAdd(dst, w * v01.x);
                    atomicAdd(dst + 1, w * v01.y);
                }
                if (m_hi < cnt) {
                    float w = swgt[r0g + 8];
                    float* dst = finalout + (size_t)sidx[r0g + 8] * N + n;
                    atomicAdd(dst, w * v23.x);
                    atomicAdd(dst + 1, w * v23.y);
                }
            }
        }
    }
}

#define TG_SMEM (int)(TILE_OFF + 2 * STG_BYTES)

// ---------------- RoPE (packed qkv, in place) ----------------
__global__ void rope_kernel(float* __restrict__ qkv) {
    int s = blockIdx.x, h = blockIdx.y, d = threadIdx.x;  // d in [0,32)
    float inv_freq = powf(1000000.0f, -(float)(2 * d) / 64.0f);
    float ang = (float)s * inv_freq;
    float sn, c;
    sincosf(ang, &sn, &c);
    float* base = (h < NHEAD)
                      ? (qkv + (size_t)s * QKV_LD + h * HDIM)
                      : (qkv + (size_t)s * QKV_LD + 1024 + (h - NHEAD) * HDIM);
    float x1 = base[d], x2 = base[d + 32];
    base[d]      = x1 * c - x2 * sn;
    base[d + 32] = x2 * c + x1 * sn;
}

// ---------------- flash attention (causal, GQA) on packed qkv ----------------
__global__ void attn_kernel(const float* __restrict__ qkv,
                            float* __restrict__ ctx) {
    extern __shared__ float sm[];
    float* Qs = sm;                 // [64][65]
    float* Ks = Qs + 64 * 65;
    float* Vs = Ks + 64 * 65;
    float* Ps = Vs + 64 * 65;

    int qt = blockIdx.x, h = blockIdx.y;
    int kvh = h >> 1;
    int tid = threadIdx.x;
    int r = tid >> 2;
    int cg = tid & 3;
    int d0 = cg * 16;

    for (int i = tid; i < 64 * 64; i += 256) {
        int rr = i >> 6, dd = i & 63;
        Qs[rr * 65 + dd] =
            qkv[(size_t)(qt * 64 + rr) * QKV_LD + h * HDIM + dd] * 0.125f;
    }

    float m = -1e30f, l = 0.f;
    float o[16];
    #pragma unroll
    for (int j = 0; j < 16; j++) o[j] = 0.f;
    int qrow_g = qt * 64 + r;

    for (int kt = 0; kt <= qt; kt++) {
        for (int i = tid; i < 64 * 64; i += 256) {
            int rr = i >> 6, dd = i & 63;
            size_t off = (size_t)(kt * 64 + rr) * QKV_LD + 1024 + kvh * HDIM + dd;
            Ks[rr * 65 + dd] = qkv[off];
            Vs[rr * 65 + dd] = qkv[off + 512];
        }
        __syncthreads();

        float sc[16];
        #pragma unroll
        for (int j = 0; j < 16; j++) sc[j] = 0.f;
        for (int kk = 0; kk < 64; kk++) {
            float a = Qs[r * 65 + kk];
            #pragma unroll
            for (int j = 0; j < 16; j++) sc[j] += a * Ks[(d0 + j) * 65 + kk];
        }
        float tmax = -1e30f;
        #pragma unroll
        for (int j = 0; j < 16; j++) {
            int cglob = kt * 64 + d0 + j;
            if (cglob > qrow_g) sc[j] = -1e30f;
            tmax = fmaxf(tmax, sc[j]);
        }
        tmax = fmaxf(tmax, __shfl_xor_sync(0xffffffffu, tmax, 1));
        tmax = fmaxf(tmax, __shfl_xor_sync(0xffffffffu, tmax, 2));
        float mnew = fmaxf(m, tmax);
        float alpha = __expf(m - mnew);
        float lsum = 0.f;
        #pragma unroll
        for (int j = 0; j < 16; j++) {
            float p = __expf(sc[j] - mnew);
            Ps[r * 65 + d0 + j] = p;
            lsum += p;
        }
        lsum += __shfl_xor_sync(0xffffffffu, lsum, 1);
        lsum += __shfl_xor_sync(0xffffffffu, lsum, 2);
        l = l * alpha + lsum;
        m = mnew;
        #pragma unroll
        for (int j = 0; j < 16; j++) o[j] *= alpha;
        __syncthreads();

        for (int c = 0; c < 64; c++) {
            float p = Ps[r * 65 + c];
            #pragma unroll
            for (int j = 0; j < 16; j++) o[j] += p * Vs[c * 65 + d0 + j];
        }
        __syncthreads();
    }

    float invl = 1.f / l;
    #pragma unroll
    for (int j = 0; j < 16; j++)
        ctx[(size_t)qrow_g * H_DIM + h * HDIM + d0 + j] = o[j] * invl;
}

// ---------------- router ----------------
__global__ void router_kernel(const float* __restrict__ xn,
                              const float* __restrict__ gw) {
    int t = blockIdx.x;
    int wid = threadIdx.x >> 5, lane = threadIdx.x & 31;
    __shared__ float logit[NEXP];
    const float* xr = xn + (size_t)t * H_DIM;
    const float* gr = gw + (size_t)wid * H_DIM;
    float s = 0.f;
    for (int i = lane; i < H_DIM; i += 32) s += xr[i] * gr[i];
    #pragma unroll
    for (int off = 16; off; off >>= 1) s += __shfl_xor_sync(0xffffffffu, s, off);
    if (lane == 0) logit[wid] = s;
    __syncthreads();
    if (threadIdx.x == 0) {
        float mx = -1e30f;
        for (int e = 0; e < NEXP; e++) mx = fmaxf(mx, logit[e]);
        float rw[NEXP], sum = 0.f;
        for (int e = 0; e < NEXP; e++) { rw[e] = expf(logit[e] - mx); sum += rw[e]; }
        float invs = 1.f / sum;
        for (int e = 0; e < NEXP; e++) rw[e] *= invs;
        int ba = 0, bb = 1;
        float best = -1.f;
        for (int a = 0; a < NEXP; a++)
            for (int b = a + 1; b < NEXP; b++) {
                float vv = rw[a] + rw[b];
                if (vv > best) { best = vv; ba = a; bb = b; }
            }
        float wa = rw[ba], wb = rw[bb];
        float inv = 1.f / (wa + wb);
        int sa = atomicAdd(&g_cnt[ba], 1);
        g_tok[ba * S_LEN + sa] = t; g_twgt[ba * S_LEN + sa] = wa * inv;
        int sb = atomicAdd(&g_cnt[bb], 1);
        g_tok[bb * S_LEN + sb] = t; g_twgt[bb * S_LEN + sb] = wb * inv;
    }
}

// ---------------- silu(s1)*s3 -> bf16 hi/lo ----------------
__global__ void silu_mul_kernel() {
    int e = blockIdx.z;
    int row = blockIdx.y;
    if (row >= g_cnt[e]) return;
    size_t off = ((size_t)e * S_LEN + row) * IDIM + blockIdx.x * 256 + threadIdx.x;
    float a = g_s1[off], b = g_s3[off];
    float gv = a * (1.f / (1.f + expf(-a))) * b;
    bf16 h = __float2bfloat16(gv);
    g_s1h[off] = h;
    g_s1l[off] = __float2bfloat16(gv - __bfloat162float(h));
}

// ---------------- launch ----------------
static void* symaddr(const void* sym) {
    void* p = nullptr;
    cudaGetSymbolAddress(&p, sym);
    return p;
}

static void conv(const float* src, void* hi, void* lo, size_t n) {
    int n4 = (int)(n / 4);
    int grid = (n4 + 255) / 256;
    if (grid > 2048) grid = 2048;
    conv_split4<<<grid, 256>>>((const float4*)src, (uint2*)hi, (uint2*)lo, n4);
}

extern "C" void kernel_launch(void* const* d_in, const int* in_sizes, int n_in,
                              void* d_out, int out_size) {
    const float* hidden = (const float*)d_in[0];
    const float* ln1    = (const float*)d_in[1];
    const float* ln2    = (const float*)d_in[2];
    const float* wq     = (const float*)d_in[3];
    const float* wk     = (const float*)d_in[4];
    const float* wv     = (const float*)d_in[5];
    const float* wo     = (const float*)d_in[6];
    const float* gate   = (const float*)d_in[7];
    const float* w1     = (const float*)d_in[8];
    const float* w2     = (const float*)d_in[9];
    const float* w3     = (const float*)d_in[10];
    float* out = (float*)d_out;

    float* xn   = (float*)symaddr(g_xn);
    bf16* xnh   = (bf16*)symaddr(g_xnh);
    bf16* xnl   = (bf16*)symaddr(g_xnl);
    float* qkv  = (float*)symaddr(g_qkv);
    float* ctx  = (float*)symaddr(g_ctx);
    bf16* ctxh  = (bf16*)symaddr(g_ctxh);
    bf16* ctxl  = (bf16*)symaddr(g_ctxl);
    float* hid  = (float*)symaddr(g_hid);
    float* s1   = (float*)symaddr(g_s1);
    float* s3   = (float*)symaddr(g_s3);
    bf16* s1h   = (bf16*)symaddr(g_s1h);
    bf16* s1l   = (bf16*)symaddr(g_s1l);
    bf16* wqkvh = (bf16*)symaddr(g_wqkvh);
    bf16* wqkvl = (bf16*)symaddr(g_wqkvl);
    bf16* woh   = (bf16*)symaddr(g_woh);
    bf16* wol   = (bf16*)symaddr(g_wol);
    bf16* w1h   = (bf16*)symaddr(g_w1h);
    bf16* w1l   = (bf16*)symaddr(g_w1l);
    bf16* w2h   = (bf16*)symaddr(g_w2h);
    bf16* w2l   = (bf16*)symaddr(g_w2l);
    bf16* w3h   = (bf16*)symaddr(g_w3h);
    bf16* w3l   = (bf16*)symaddr(g_w3l);

    cudaFuncSetAttribute(tgemm<0>, cudaFuncAttributeMaxDynamicSharedMemorySize, TG_SMEM);
    cudaFuncSetAttribute(tgemm<1>, cudaFuncAttributeMaxDynamicSharedMemorySize, TG_SMEM);
    cudaFuncSetAttribute(tgemm<2>, cudaFuncAttributeMaxDynamicSharedMemorySize, TG_SMEM);
    cudaFuncSetAttribute(tgemm<3>, cudaFuncAttributeMaxDynamicSharedMemorySize, TG_SMEM);
    int attn_smem = 4 * 64 * 65 * (int)sizeof(float);
    cudaFuncSetAttribute(attn_kernel, cudaFuncAttributeMaxDynamicSharedMemorySize,
                         attn_smem);

    reset_kernel<<<1, 32>>>();

    // weight conversions (fp32 -> bf16 hi/lo)
    conv(wq, wqkvh, wqkvl, (size_t)1024 * 1024);
    conv(wk, wqkvh + (size_t)1024 * 1024, wqkvl + (size_t)1024 * 1024,
         (size_t)512 * 1024);
    conv(wv, wqkvh + (size_t)1536 * 1024, wqkvl + (size_t)1536 * 1024,
         (size_t)512 * 1024);
    conv(wo, woh, wol, (size_t)1024 * 1024);
    conv(w1, w1h, w1l, (size_t)NEXP * IDIM * H_DIM);
    conv(w2, w2h, w2l, (size_t)NEXP * H_DIM * IDIM);
    conv(w3, w3h, w3l, (size_t)NEXP * IDIM * H_DIM);

    rmsnorm_kernel<<<S_LEN, 256>>>(hidden, ln1, xn, xnh, xnl);

    // packed QKV projection: [2048 tok] x [2048 rows of wqkv]
    tgemm<0><<<dim3(16, 16, 1), 256, TG_SMEM>>>(
        xnh, xnl, wqkvh, wqkvl, qkv, S_LEN, QKV_LD, H_DIM,
        nullptr, nullptr, nullptr);

    rope_kernel<<<dim3(S_LEN, NHEAD + KVHEAD), 32>>>(qkv);

    attn_kernel<<<dim3(S_LEN / 64, NHEAD), 256, attn_smem>>>(qkv, ctx);

    conv(ctx, ctxh, ctxl, (size_t)S_LEN * H_DIM);

    tgemm<1><<<dim3(8, 16, 1), 256, TG_SMEM>>>(
        ctxh, ctxl, woh, wol, hid, S_LEN, H_DIM, NHEAD * HDIM,
        hidden, out, nullptr);

    rmsnorm_kernel<<<S_LEN, 256>>>(hid, ln2, xn, xnh, xnl);
    router_kernel<<<S_LEN, 256>>>(xn, gate);

    tgemm<2><<<dim3(IDIM / 128, S_LEN / 128, NEXP), 256, TG_SMEM>>>(
        xnh, xnl, w1h, w1l, s1, S_LEN, IDIM, H_DIM, nullptr, nullptr, nullptr);
    tgemm<2><<<dim3(IDIM / 128, S_LEN / 128, NEXP), 256, TG_SMEM>>>(
        xnh, xnl, w3h, w3l, s3, S_LEN, IDIM, H_DIM, nullptr, nullptr, nullptr);

    silu_mul_kernel<<<dim3(IDIM / 256, S_LEN, NEXP), 256>>>();

    tgemm<3><<<dim3(H_DIM / 128, S_LEN / 128, NEXP), 256, TG_SMEM>>>(
        s1h, s1l, w2h, w2l, nullptr, S_LEN, H_DIM, IDIM,
        nullptr, nullptr, out);
}

// round 5
// speedup vs baseline: 1.7744x; 1.5910x over previous
#include <cuda_runtime.h>
#include <cuda_bf16.h>
#include <math.h>
#include <stdint.h>

#define S_LEN 2048
#define H_DIM 1024
#define NHEAD 16
#define KVHEAD 8
#define HDIM 64
#define NEXP 8
#define IDIM 3584
#define I2 7168
#define QKV_LD 2048

typedef __nv_bfloat16 bf16;

// ---------------- scratch ----------------
__device__ float g_xn[S_LEN * H_DIM];
__device__ __align__(16) bf16 g_xnh[S_LEN * H_DIM];
__device__ __align__(16) bf16 g_xnl[S_LEN * H_DIM];
__device__ float g_qkv[S_LEN * QKV_LD];
__device__ __align__(16) bf16 g_ctxh[S_LEN * H_DIM];
__device__ __align__(16) bf16 g_ctxl[S_LEN * H_DIM];
__device__ float g_hid[S_LEN * H_DIM];
__device__ int   g_cnt[NEXP];
__device__ int   g_tok[NEXP * S_LEN];
__device__ float g_twgt[NEXP * S_LEN];
__device__ __align__(16) bf16 g_s13h[(size_t)NEXP * S_LEN * I2];
__device__ __align__(16) bf16 g_s13l[(size_t)NEXP * S_LEN * I2];
__device__ __align__(16) bf16 g_s1h[(size_t)NEXP * S_LEN * IDIM];
__device__ __align__(16) bf16 g_s1l[(size_t)NEXP * S_LEN * IDIM];
__device__ __align__(16) bf16 g_wqkvh[QKV_LD * H_DIM];
__device__ __align__(16) bf16 g_wqkvl[QKV_LD * H_DIM];
__device__ __align__(16) bf16 g_woh[H_DIM * H_DIM];
__device__ __align__(16) bf16 g_wol[H_DIM * H_DIM];
__device__ __align__(16) bf16 g_w13h[(size_t)NEXP * I2 * H_DIM];
__device__ __align__(16) bf16 g_w13l[(size_t)NEXP * I2 * H_DIM];
__device__ __align__(16) bf16 g_w2h[(size_t)NEXP * H_DIM * IDIM];
__device__ __align__(16) bf16 g_w2l[(size_t)NEXP * H_DIM * IDIM];

// ---------------- ptx helpers ----------------
__device__ __forceinline__ uint32_t smem_u32(const void* p) {
    uint32_t a;
    asm("{ .reg .u64 t; cvta.to.shared.u64 t, %1; cvt.u32.u64 %0, t; }"
        : "=r"(a) : "l"(p));
    return a;
}
__device__ __forceinline__ void cp16(uint32_t dst, const void* src) {
    asm volatile("cp.async.cg.shared.global [%0], [%1], 16;"
                 :: "r"(dst), "l"(src) : "memory");
}
__device__ __forceinline__ void cp_commit() {
    asm volatile("cp.async.commit_group;" ::: "memory");
}
template <int N>
__device__ __forceinline__ void cp_wait() {
    asm volatile("cp.async.wait_group %0;" :: "n"(N) : "memory");
}
__device__ __forceinline__ void ldsm4(uint32_t& r0, uint32_t& r1, uint32_t& r2,
                                      uint32_t& r3, uint32_t a) {
    asm volatile("ldmatrix.sync.aligned.m8n8.x4.shared.b16 {%0,%1,%2,%3}, [%4];"
                 : "=r"(r0), "=r"(r1), "=r"(r2), "=r"(r3) : "r"(a));
}
__device__ __forceinline__ void ldsm2(uint32_t& r0, uint32_t& r1, uint32_t a) {
    asm volatile("ldmatrix.sync.aligned.m8n8.x2.shared.b16 {%0,%1}, [%2];"
                 : "=r"(r0), "=r"(r1) : "r"(a));
}
__device__ __forceinline__ void mma_bf16(float& d0, float& d1, float& d2, float& d3,
                                         uint32_t a0, uint32_t a1, uint32_t a2,
                                         uint32_t a3, uint32_t b0, uint32_t b1) {
    asm volatile(
        "mma.sync.aligned.m16n8k16.row.col.f32.bf16.bf16.f32 "
        "{%0,%1,%2,%3}, {%4,%5,%6,%7}, {%8,%9}, {%0,%1,%2,%3};"
        : "+f"(d0), "+f"(d1), "+f"(d2), "+f"(d3)
        : "r"(a0), "r"(a1), "r"(a2), "r"(a3), "r"(b0), "r"(b1));
}
__device__ __forceinline__ uint32_t pack_bf2(bf16 a, bf16 b) {
    __nv_bfloat162 t;
    t.x = a; t.y = b;
    return *reinterpret_cast<uint32_t*>(&t);
}

// ---------------- reset ----------------
__global__ void reset_kernel() {
    if (threadIdx.x < NEXP) g_cnt[threadIdx.x] = 0;
}

// ---------------- fused weight conversion: all weights in one launch ----------
// seg: 0 wq, 1 wk, 2 wv, 3 wo, 4 w2, 5 w1->w13(lo half), 6 w3->w13(hi half)
__global__ void conv_all_kernel(const float4* __restrict__ wq,
                                const float4* __restrict__ wk,
                                const float4* __restrict__ wv,
                                const float4* __restrict__ wo,
                                const float4* __restrict__ w1,
                                const float4* __restrict__ w2,
                                const float4* __restrict__ w3) {
    int seg = blockIdx.y;
    const float4* src;
    uint2* hi;
    uint2* lo;
    int n4;
    bool strided = false;
    int off4 = 0;
    switch (seg) {
        case 0: src = wq; hi = (uint2*)g_wqkvh; lo = (uint2*)g_wqkvl;
                n4 = 262144; break;
        case 1: src = wk; hi = (uint2*)(g_wqkvh + 1048576);
                lo = (uint2*)(g_wqkvl + 1048576); n4 = 131072; break;
        case 2: src = wv; hi = (uint2*)(g_wqkvh + 1572864);
                lo = (uint2*)(g_wqkvl + 1572864); n4 = 131072; break;
        case 3: src = wo; hi = (uint2*)g_woh; lo = (uint2*)g_wol;
                n4 = 262144; break;
        case 4: src = w2; hi = (uint2*)g_w2h; lo = (uint2*)g_w2l;
                n4 = 7340032; break;
        case 5: src = w1; hi = (uint2*)g_w13h; lo = (uint2*)g_w13l;
                n4 = 7340032; strided = true; off4 = 0; break;
        default: src = w3; hi = (uint2*)g_w13h; lo = (uint2*)g_w13l;
                n4 = 7340032; strided = true; off4 = 917504; break;
    }
    for (int i = blockIdx.x * blockDim.x + threadIdx.x; i < n4;
         i += gridDim.x * blockDim.x) {
        float4 v = src[i];
        bf16 h0 = __float2bfloat16(v.x), h1 = __float2bfloat16(v.y);
        bf16 h2 = __float2bfloat16(v.z), h3 = __float2bfloat16(v.w);
        bf16 l0 = __float2bfloat16(v.x - __bfloat162float(h0));
        bf16 l1 = __float2bfloat16(v.y - __bfloat162float(h1));
        bf16 l2 = __float2bfloat16(v.z - __bfloat162float(h2));
        bf16 l3 = __float2bfloat16(v.w - __bfloat162float(h3));
        int d = i;
        if (strided) {
            int e = i / 917504;
            int rem = i - e * 917504;
            d = e * 1835008 + off4 + rem;
        }
        hi[d] = make_uint2(pack_bf2(h0, h1), pack_bf2(h2, h3));
        lo[d] = make_uint2(pack_bf2(l0, l1), pack_bf2(l2, l3));
    }
}

// ---------------- rmsnorm (fp32 + bf16 hi/lo out) ----------------
__global__ void rmsnorm_kernel(const float* __restrict__ x,
                               const float* __restrict__ w,
                               float* __restrict__ o,
                               bf16* __restrict__ oh, bf16* __restrict__ ol) {
    int row = blockIdx.x;
    const float* xr = x + (size_t)row * H_DIM;
    float s = 0.f;
    for (int i = threadIdx.x; i < H_DIM; i += 256) {
        float v = xr[i];
        s += v * v;
    }
    __shared__ float red[8];
    int lane = threadIdx.x & 31, wid = threadIdx.x >> 5;
    #pragma unroll
    for (int off = 16; off; off >>= 1) s += __shfl_xor_sync(0xffffffffu, s, off);
    if (lane == 0) red[wid] = s;
    __syncthreads();
    if (wid == 0) {
        float t = (lane < 8) ? red[lane] : 0.f;
        #pragma unroll
        for (int off = 4; off; off >>= 1) t += __shfl_xor_sync(0xffffffffu, t, off);
        if (lane == 0) red[0] = t;
    }
    __syncthreads();
    float inv = rsqrtf(red[0] * (1.f / H_DIM) + 1e-6f);
    for (int i = threadIdx.x; i < H_DIM; i += 256) {
        float val = w[i] * xr[i] * inv;
        size_t off = (size_t)row * H_DIM + i;
        o[off] = val;
        bf16 h = __float2bfloat16(val);
        oh[off] = h;
        ol[off] = __float2bfloat16(val - __bfloat162float(h));
    }
}

// ---------------- tensor-core NT GEMM via mma.sync (bf16-split 3-term) --------
// MODE 0: fp32 store   MODE 1: +resid dual fp32 store
// MODE 2: gathered A rows, bf16 hi/lo store   MODE 3: weighted atomic scatter
#define STG_BYTES 40960u
#define TILE_OFF 1024u

template <int MODE>
__global__ void __launch_bounds__(256, 2) tgemm(
    const bf16* __restrict__ Ah, const bf16* __restrict__ Al,
    const bf16* __restrict__ Bhb, const bf16* __restrict__ Blb,
    float* __restrict__ Cb, int M, int N, int K,
    const float* __restrict__ resid, float* __restrict__ out2,
    float* __restrict__ finalout,
    bf16* __restrict__ Chb, bf16* __restrict__ Clb) {
    int z = blockIdx.z;
    int cnt = M;
    const bf16* Bh = Bhb;
    const bf16* Bl = Blb;
    bf16* Ch = Chb;
    bf16* Cl = Clb;
    if (MODE == 2) {
        cnt = g_cnt[z];
        if ((int)blockIdx.y * 128 >= cnt) return;
        Bh = Bhb + (size_t)z * I2 * H_DIM;
        Bl = Blb + (size_t)z * I2 * H_DIM;
        Ch = Chb + (size_t)z * S_LEN * I2;
        Cl = Clb + (size_t)z * S_LEN * I2;
    }
    if (MODE == 3) {
        cnt = g_cnt[z];
        if ((int)blockIdx.y * 128 >= cnt) return;
        Ah = Ah + (size_t)z * S_LEN * IDIM;
        Al = Al + (size_t)z * S_LEN * IDIM;
        Bh = Bhb + (size_t)z * H_DIM * IDIM;
        Bl = Blb + (size_t)z * H_DIM * IDIM;
    }

    extern __shared__ char smem[];
    uint32_t sb = smem_u32(smem);
    int* sidx = (int*)smem;
    float* swgt = (float*)(smem + 512);
    uint32_t tb = sb + TILE_OFF;

    int tid = threadIdx.x;
    int lane = tid & 31, wid = tid >> 5;
    int wr = wid >> 2, wc = wid & 3;
    int m0 = blockIdx.y * 128, n0 = blockIdx.x * 128;

    if (MODE == 2 || MODE == 3) {
        if (tid < 128) {
            int m = m0 + tid;
            sidx[tid] = (m < cnt) ? g_tok[z * S_LEN + m] : 0;
            swgt[tid] = (m < cnt) ? g_twgt[z * S_LEN + m] : 0.f;
        }
        __syncthreads();
    }

    int crow = tid >> 2;
    int cch = tid & 3;
    int arow0, arow1;
    if (MODE == 2) {
        arow0 = sidx[crow];
        arow1 = sidx[crow + 64];
    } else {
        arow0 = m0 + crow;
        arow1 = m0 + crow + 64;
    }
    const bf16* pAh0 = Ah + (size_t)arow0 * K + cch * 8;
    const bf16* pAl0 = Al + (size_t)arow0 * K + cch * 8;
    const bf16* pAh1 = Ah + (size_t)arow1 * K + cch * 8;
    const bf16* pAl1 = Al + (size_t)arow1 * K + cch * 8;
    const bf16* pBh0 = Bh + (size_t)(n0 + crow) * K + cch * 8;
    const bf16* pBl0 = Bl + (size_t)(n0 + crow) * K + cch * 8;
    const bf16* pBh1 = Bh + (size_t)(n0 + crow + 64) * K + cch * 8;
    const bf16* pBl1 = Bl + (size_t)(n0 + crow + 64) * K + cch * 8;
    uint32_t d0 = (uint32_t)crow * 80u + (uint32_t)cch * 16u;
    uint32_t d1 = d0 + 64u * 80u;

    float acc[4][4][4];
    #pragma unroll
    for (int a = 0; a < 4; a++)
        #pragma unroll
        for (int b = 0; b < 4; b++)
            #pragma unroll
            for (int c = 0; c < 4; c++) acc[a][b][c] = 0.f;

    int nst = K / 32;

    {
        uint32_t st = tb;
        cp16(st + d0, pAh0);
        cp16(st + d0 + 10240u, pAl0);
        cp16(st + d1, pAh1);
        cp16(st + d1 + 10240u, pAl1);
        cp16(st + 20480u + d0, pBh0);
        cp16(st + 20480u + d0 + 10240u, pBl0);
        cp16(st + 20480u + d1, pBh1);
        cp16(st + 20480u + d1 + 10240u, pBl1);
        cp_commit();
    }

    for (int s = 0; s < nst; s++) {
        if (s + 1 < nst) {
            uint32_t st = tb + (uint32_t)((s + 1) & 1) * STG_BYTES;
            size_t ko = (size_t)(s + 1) * 32;
            cp16(st + d0, pAh0 + ko);
            cp16(st + d0 + 10240u, pAl0 + ko);
            cp16(st + d1, pAh1 + ko);
            cp16(st + d1 + 10240u, pAl1 + ko);
            cp16(st + 20480u + d0, pBh0 + ko);
            cp16(st + 20480u + d0 + 10240u, pBl0 + ko);
            cp16(st + 20480u + d1, pBh1 + ko);
            cp16(st + 20480u + d1 + 10240u, pBl1 + ko);
            cp_commit();
            cp_wait<1>();
        } else {
            cp_wait<0>();
        }
        __syncthreads();

        uint32_t st = tb + (uint32_t)(s & 1) * STG_BYTES;
        #pragma unroll
        for (int kk = 0; kk < 2; kk++) {
            uint32_t bh[4][2], bl[4][2];
            uint32_t bbase = st + 20480u +
                             (uint32_t)(wc * 32 + (lane & 7)) * 80u +
                             (uint32_t)(kk * 32 + ((lane >> 3) & 1) * 16);
            #pragma unroll
            for (int nf = 0; nf < 4; nf++) {
                ldsm2(bh[nf][0], bh[nf][1], bbase + nf * 8 * 80u);
                ldsm2(bl[nf][0], bl[nf][1], bbase + nf * 8 * 80u + 10240u);
            }
            uint32_t abase = st + (uint32_t)(wr * 64 + (lane & 15)) * 80u +
                             (uint32_t)(kk * 32 + (lane >> 4) * 16);
            #pragma unroll
            for (int mf = 0; mf < 4; mf++) {
                uint32_t ah[4], al[4];
                ldsm4(ah[0], ah[1], ah[2], ah[3], abase + mf * 16 * 80u);
                ldsm4(al[0], al[1], al[2], al[3], abase + mf * 16 * 80u + 10240u);
                // term-major ordering: consecutive MMAs target different
                // accumulators (nf varies) -> no dependent HMMA chains
                #pragma unroll
                for (int nf = 0; nf < 4; nf++)
                    mma_bf16(acc[mf][nf][0], acc[mf][nf][1], acc[mf][nf][2],
                             acc[mf][nf][3], ah[0], ah[1], ah[2], ah[3],
                             bh[nf][0], bh[nf][1]);
                #pragma unroll
                for (int nf = 0; nf < 4; nf++)
                    mma_bf16(acc[mf][nf][0], acc[mf][nf][1], acc[mf][nf][2],
                             acc[mf][nf][3], ah[0], ah[1], ah[2], ah[3],
                             bl[nf][0], bl[nf][1]);
                #pragma unroll
                for (int nf = 0; nf < 4; nf++)
                    mma_bf16(acc[mf][nf][0], acc[mf][nf][1], acc[mf][nf][2],
                             acc[mf][nf][3], al[0], al[1], al[2], al[3],
                             bh[nf][0], bh[nf][1]);
            }
        }
        __syncthreads();
    }

    // epilogue
    int g = lane >> 2, cpr = (lane & 3) * 2;
    #pragma unroll
    for (int mf = 0; mf < 4; mf++) {
        int r0g = wr * 64 + mf * 16 + g;
        int m_lo = m0 + r0g, m_hi = m_lo + 8;
        #pragma unroll
        for (int nf = 0; nf < 4; nf++) {
            int n = n0 + wc * 32 + nf * 8 + cpr;
            float2 v01 = make_float2(acc[mf][nf][0], acc[mf][nf][1]);
            float2 v23 = make_float2(acc[mf][nf][2], acc[mf][nf][3]);
            if (MODE == 0) {
                *(float2*)(Cb + (size_t)m_lo * N + n) = v01;
                *(float2*)(Cb + (size_t)m_hi * N + n) = v23;
            } else if (MODE == 1) {
                size_t o_lo = (size_t)m_lo * N + n;
                size_t o_hi = (size_t)m_hi * N + n;
                float2 r0 = *(const float2*)(resid + o_lo);
                float2 r1 = *(const float2*)(resid + o_hi);
                v01.x += r0.x; v01.y += r0.y;
                v23.x += r1.x; v23.y += r1.y;
                *(float2*)(Cb + o_lo) = v01;
                *(float2*)(out2 + o_lo) = v01;
                *(float2*)(Cb + o_hi) = v23;
                *(float2*)(out2 + o_hi) = v23;
            } else if (MODE == 2) {
                if (m_lo < cnt) {
                    size_t o = (size_t)m_lo * N + n;
                    bf16 h0 = __float2bfloat16(v01.x);
                    bf16 h1 = __float2bfloat16(v01.y);
                    bf16 l0 = __float2bfloat16(v01.x - __bfloat162float(h0));
                    bf16 l1 = __float2bfloat16(v01.y - __bfloat162float(h1));
                    *(uint32_t*)(Ch + o) = pack_bf2(h0, h1);
                    *(uint32_t*)(Cl + o) = pack_bf2(l0, l1);
                }
                if (m_hi < cnt) {
                    size_t o = (size_t)m_hi * N + n;
                    bf16 h0 = __float2bfloat16(v23.x);
                    bf16 h1 = __float2bfloat16(v23.y);
                    bf16 l0 = __float2bfloat16(v23.x - __bfloat162float(h0));
                    bf16 l1 = __float2bfloat16(v23.y - __bfloat162float(h1));
                    *(uint32_t*)(Ch + o) = pack_bf2(h0, h1);
                    *(uint32_t*)(Cl + o) = pack_bf2(l0, l1);
                }
            } else {
                if (m_lo < cnt) {
                    float w = swgt[r0g];
                    float* dst = finalout + (size_t)sidx[r0g] * N + n;
                    atomicAdd(dst, w * v01.x);
                    atomicAdd(dst + 1, w * v01.y);
                }
                if (m_hi < cnt) {
                    float w = swgt[r0g + 8];
                    float* dst = finalout + (size_t)sidx[r0g + 8] * N + n;
                    atomicAdd(dst, w * v23.x);
                    atomicAdd(dst + 1, w * v23.y);
                }
            }
        }
    }
}

#define TG_SMEM (int)(TILE_OFF + 2 * STG_BYTES)

// ---------------- RoPE (packed qkv, in place) ----------------
__global__ void rope_kernel(float* __restrict__ qkv) {
    int s = blockIdx.x, h = blockIdx.y, d = threadIdx.x;
    float inv_freq = powf(1000000.0f, -(float)(2 * d) / 64.0f);
    float ang = (float)s * inv_freq;
    float sn, c;
    sincosf(ang, &sn, &c);
    float* base = (h < NHEAD)
                      ? (qkv + (size_t)s * QKV_LD + h * HDIM)
                      : (qkv + (size_t)s * QKV_LD + 1024 + (h - NHEAD) * HDIM);
    float x1 = base[d], x2 = base[d + 32];
    base[d]      = x1 * c - x2 * sn;
    base[d + 32] = x2 * c + x1 * sn;
}

// ---------------- flash attention (causal, GQA), vectorized, bf16 hi/lo out --
#define ALD 68
__global__ void attn_kernel(const float* __restrict__ qkv,
                            bf16* __restrict__ ctxh, bf16* __restrict__ ctxl) {
    extern __shared__ float sm[];
    float* Qs = sm;                 // [64][68]
    float* Ks = Qs + 64 * ALD;
    float* Vs = Ks + 64 * ALD;
    float* Ps = Vs + 64 * ALD;

    int qt = blockIdx.x, h = blockIdx.y;
    int kvh = h >> 1;
    int tid = threadIdx.x;
    int r = tid >> 2;
    int cg = tid & 3;
    int d0 = cg * 16;

    for (int i = tid; i < 64 * 16; i += 256) {
        int rr = i >> 4, dd = (i & 15) * 4;
        float4 v = *(const float4*)(qkv + (size_t)(qt * 64 + rr) * QKV_LD +
                                    h * HDIM + dd);
        v.x *= 0.125f; v.y *= 0.125f; v.z *= 0.125f; v.w *= 0.125f;
        *(float4*)&Qs[rr * ALD + dd] = v;
    }

    float m = -1e30f, l = 0.f;
    float o[16];
    #pragma unroll
    for (int j = 0; j < 16; j++) o[j] = 0.f;
    int qrow_g = qt * 64 + r;

    for (int kt = 0; kt <= qt; kt++) {
        for (int i = tid; i < 64 * 16; i += 256) {
            int rr = i >> 4, dd = (i & 15) * 4;
            size_t off = (size_t)(kt * 64 + rr) * QKV_LD + 1024 + kvh * HDIM + dd;
            *(float4*)&Ks[rr * ALD + dd] = *(const float4*)(qkv + off);
            *(float4*)&Vs[rr * ALD + dd] = *(const float4*)(qkv + off + 512);
        }
        __syncthreads();

        float sc[16];
        #pragma unroll
        for (int j = 0; j < 16; j++) sc[j] = 0.f;
        for (int kk = 0; kk < 64; kk += 4) {
            float4 qv = *(const float4*)&Qs[r * ALD + kk];
            #pragma unroll
            for (int j = 0; j < 16; j++) {
                float4 kv = *(const float4*)&Ks[(d0 + j) * ALD + kk];
                sc[j] += qv.x * kv.x + qv.y * kv.y + qv.z * kv.z + qv.w * kv.w;
            }
        }
        float tmax = -1e30f;
        #pragma unroll
        for (int j = 0; j < 16; j++) {
            int cglob = kt * 64 + d0 + j;
            if (cglob > qrow_g) sc[j] = -1e30f;
            tmax = fmaxf(tmax, sc[j]);
        }
        tmax = fmaxf(tmax, __shfl_xor_sync(0xffffffffu, tmax, 1));
        tmax = fmaxf(tmax, __shfl_xor_sync(0xffffffffu, tmax, 2));
        float mnew = fmaxf(m, tmax);
        float alpha = __expf(m - mnew);
        float lsum = 0.f;
        #pragma unroll
        for (int j = 0; j < 16; j++) {
            float p = __expf(sc[j] - mnew);
            Ps[r * ALD + d0 + j] = p;
            lsum += p;
        }
        lsum += __shfl_xor_sync(0xffffffffu, lsum, 1);
        lsum += __shfl_xor_sync(0xffffffffu, lsum, 2);
        l = l * alpha + lsum;
        m = mnew;
        #pragma unroll
        for (int j = 0; j < 16; j++) o[j] *= alpha;
        __syncthreads();

        for (int c = 0; c < 64; c++) {
            float p = Ps[r * ALD + c];
            #pragma unroll
            for (int jq = 0; jq < 4; jq++) {
                float4 vv = *(const float4*)&Vs[c * ALD + d0 + jq * 4];
                o[jq * 4 + 0] += p * vv.x;
                o[jq * 4 + 1] += p * vv.y;
                o[jq * 4 + 2] += p * vv.z;
                o[jq * 4 + 3] += p * vv.w;
            }
        }
        __syncthreads();
    }

    float invl = 1.f / l;
    size_t ob = (size_t)qrow_g * H_DIM + h * HDIM + d0;
    #pragma unroll
    for (int j = 0; j < 16; j++) {
        float val = o[j] * invl;
        bf16 hh = __float2bfloat16(val);
        ctxh[ob + j] = hh;
        ctxl[ob + j] = __float2bfloat16(val - __bfloat162float(hh));
    }
}

// ---------------- router ----------------
__global__ void router_kernel(const float* __restrict__ xn,
                              const float* __restrict__ gw) {
    int t = blockIdx.x;
    int wid = threadIdx.x >> 5, lane = threadIdx.x & 31;
    __shared__ float logit[NEXP];
    const float* xr = xn + (size_t)t * H_DIM;
    const float* gr = gw + (size_t)wid * H_DIM;
    float s = 0.f;
    for (int i = lane; i < H_DIM; i += 32) s += xr[i] * gr[i];
    #pragma unroll
    for (int off = 16; off; off >>= 1) s += __shfl_xor_sync(0xffffffffu, s, off);
    if (lane == 0) logit[wid] = s;
    __syncthreads();
    if (threadIdx.x == 0) {
        float mx = -1e30f;
        for (int e = 0; e < NEXP; e++) mx = fmaxf(mx, logit[e]);
        float rw[NEXP], sum = 0.f;
        for (int e = 0; e < NEXP; e++) { rw[e] = expf(logit[e] - mx); sum += rw[e]; }
        float invs = 1.f / sum;
        for (int e = 0; e < NEXP; e++) rw[e] *= invs;
        int ba = 0, bb = 1;
        float best = -1.f;
        for (int a = 0; a < NEXP; a++)
            for (int b = a + 1; b < NEXP; b++) {
                float vv = rw[a] + rw[b];
                if (vv > best) { best = vv; ba = a; bb = b; }
            }
        float wa = rw[ba], wb = rw[bb];
        float inv = 1.f / (wa + wb);
        int sa = atomicAdd(&g_cnt[ba], 1);
        g_tok[ba * S_LEN + sa] = t; g_twgt[ba * S_LEN + sa] = wa * inv;
        int sb = atomicAdd(&g_cnt[bb], 1);
        g_tok[bb * S_LEN + sb] = t; g_twgt[bb * S_LEN + sb] = wb * inv;
    }
}

// ---------------- silu(h1)*h3 from fused s13 (bf16 hi/lo in & out) -----------
__global__ void silu_mul_kernel() {
    int e = blockIdx.z;
    int row = blockIdx.y;
    if (row >= g_cnt[e]) return;
    int i = blockIdx.x * 256 + threadIdx.x;
    size_t base = ((size_t)e * S_LEN + row) * I2;
    float a = __bfloat162float(g_s13h[base + i]) +
              __bfloat162float(g_s13l[base + i]);
    float b = __bfloat162float(g_s13h[base + i + IDIM]) +
              __bfloat162float(g_s13l[base + i + IDIM]);
    float gv = a * (1.f / (1.f + expf(-a))) * b;
    size_t o = ((size_t)e * S_LEN + row) * IDIM + i;
    bf16 h = __float2bfloat16(gv);
    g_s1h[o] = h;
    g_s1l[o] = __float2bfloat16(gv - __bfloat162float(h));
}

// ---------------- launch ----------------
static void* symaddr(const void* sym) {
    void* p = nullptr;
    cudaGetSymbolAddress(&p, sym);
    return p;
}

extern "C" void kernel_launch(void* const* d_in, const int* in_sizes, int n_in,
                              void* d_out, int out_size) {
    const float* hidden = (const float*)d_in[0];
    const float* ln1    = (const float*)d_in[1];
    const float* ln2    = (const float*)d_in[2];
    const float* wq     = (const float*)d_in[3];
    const float* wk     = (const float*)d_in[4];
    const float* wv     = (const float*)d_in[5];
    const float* wo     = (const float*)d_in[6];
    const float* gate   = (const float*)d_in[7];
    const float* w1     = (const float*)d_in[8];
    const float* w2     = (const float*)d_in[9];
    const float* w3     = (const float*)d_in[10];
    float* out = (float*)d_out;

    float* xn   = (float*)symaddr(g_xn);
    bf16* xnh   = (bf16*)symaddr(g_xnh);
    bf16* xnl   = (bf16*)symaddr(g_xnl);
    float* qkv  = (float*)symaddr(g_qkv);
    bf16* ctxh  = (bf16*)symaddr(g_ctxh);
    bf16* ctxl  = (bf16*)symaddr(g_ctxl);
    float* hid  = (float*)symaddr(g_hid);
    bf16* s13h  = (bf16*)symaddr(g_s13h);
    bf16* s13l  = (bf16*)symaddr(g_s13l);
    bf16* s1h   = (bf16*)symaddr(g_s1h);
    bf16* s1l   = (bf16*)symaddr(g_s1l);
    bf16* wqkvh = (bf16*)symaddr(g_wqkvh);
    bf16* wqkvl = (bf16*)symaddr(g_wqkvl);
    bf16* woh   = (bf16*)symaddr(g_woh);
    bf16* wol   = (bf16*)symaddr(g_wol);
    bf16* w13h  = (bf16*)symaddr(g_w13h);
    bf16* w13l  = (bf16*)symaddr(g_w13l);
    bf16* w2h   = (bf16*)symaddr(g_w2h);
    bf16* w2l   = (bf16*)symaddr(g_w2l);

    cudaFuncSetAttribute(tgemm<0>, cudaFuncAttributeMaxDynamicSharedMemorySize, TG_SMEM);
    cudaFuncSetAttribute(tgemm<1>, cudaFuncAttributeMaxDynamicSharedMemorySize, TG_SMEM);
    cudaFuncSetAttribute(tgemm<2>, cudaFuncAttributeMaxDynamicSharedMemorySize, TG_SMEM);
    cudaFuncSetAttribute(tgemm<3>, cudaFuncAttributeMaxDynamicSharedMemorySize, TG_SMEM);
    int attn_smem = 4 * 64 * ALD * (int)sizeof(float);
    cudaFuncSetAttribute(attn_kernel, cudaFuncAttributeMaxDynamicSharedMemorySize,
                         attn_smem);

    // 1: all weight conversions in one launch
    conv_all_kernel<<<dim3(2048, 7), 256>>>(
        (const float4*)wq, (const float4*)wk, (const float4*)wv,
        (const float4*)wo, (const float4*)w1, (const float4*)w2,
        (const float4*)w3);

    // 2: rmsnorm 1
    rmsnorm_kernel<<<S_LEN, 256>>>(hidden, ln1, xn, xnh, xnl);

    // 3: packed QKV projection
    tgemm<0><<<dim3(16, 16, 1), 256, TG_SMEM>>>(
        xnh, xnl, wqkvh, wqkvl, qkv, S_LEN, QKV_LD, H_DIM,
        nullptr, nullptr, nullptr, nullptr, nullptr);

    // 4: rope
    rope_kernel<<<dim3(S_LEN, NHEAD + KVHEAD), 32>>>(qkv);

    // 5: attention (writes bf16 ctx directly)
    attn_kernel<<<dim3(S_LEN / 64, NHEAD), 256, attn_smem>>>(qkv, ctxh, ctxl);

    // 6: wo projection + residual (dual-store hid & out)
    tgemm<1><<<dim3(8, 16, 1), 256, TG_SMEM>>>(
        ctxh, ctxl, woh, wol, hid, S_LEN, H_DIM, H_DIM,
        hidden, out, nullptr, nullptr, nullptr);

    // 7: rmsnorm 2
    rmsnorm_kernel<<<S_LEN, 256>>>(hid, ln2, xn, xnh, xnl);

    // 8-9: router
    reset_kernel<<<1, 32>>>();
    router_kernel<<<S_LEN, 256>>>(xn, gate);

    // 10: fused w1|w3 GEMM (N=7168), bf16 hi/lo epilogue
    tgemm<2><<<dim3(I2 / 128, S_LEN / 128, NEXP), 256, TG_SMEM>>>(
        xnh, xnl, w13h, w13l, nullptr, S_LEN, I2, H_DIM,
        nullptr, nullptr, nullptr, s13h, s13l);

    // 11: silu * mul
    silu_mul_kernel<<<dim3(IDIM / 256, S_LEN, NEXP), 256>>>();

    // 12: w2 GEMM with weighted atomic scatter into out
    tgemm<3><<<dim3(H_DIM / 128, S_LEN / 128, NEXP), 256, TG_SMEM>>>(
        s1h, s1l, w2h, w2l, nullptr, S_LEN, H_DIM, IDIM,
        nullptr, nullptr, out, nullptr, nullptr);
}

// round 16
// speedup vs baseline: 1.9939x; 1.1237x over previous
#include <cuda_runtime.h>
#include <cuda_fp16.h>
#include <math.h>
#include <stdint.h>

#define S_LEN 2048
#define H_DIM 1024
#define NHEAD 16
#define KVHEAD 8
#define HDIM 64
#define NEXP 8
#define IDIM 3584
#define I2 7168
#define QKV_LD 2048

// all fp16 operands are stored pre-scaled by 64; GEMM epilogues divide by 4096.
#define OPSCALE 64.0f
#define INVACC (1.0f / 4096.0f)

// ---------------- scratch ----------------
__device__ float g_xn[S_LEN * H_DIM];
__device__ __align__(16) half g_xnh[S_LEN * H_DIM];
__device__ __align__(16) half g_xnl[S_LEN * H_DIM];
__device__ float g_qkv[S_LEN * QKV_LD];
__device__ __align__(16) half g_ctxh[S_LEN * H_DIM];
__device__ __align__(16) half g_ctxl[S_LEN * H_DIM];
__device__ float g_hid[S_LEN * H_DIM];
__device__ int   g_cnt[NEXP];
__device__ int   g_tok[NEXP * S_LEN];
__device__ float g_twgt[NEXP * S_LEN];
__device__ __align__(16) half g_s13h[(size_t)NEXP * S_LEN * I2];
__device__ __align__(16) half g_s1h[(size_t)NEXP * S_LEN * IDIM];
__device__ __align__(16) half g_wqkvh[QKV_LD * H_DIM];
__device__ __align__(16) half g_woh[H_DIM * H_DIM];
__device__ __align__(16) half g_w13h[(size_t)NEXP * I2 * H_DIM];
__device__ __align__(16) half g_w2h[(size_t)NEXP * H_DIM * IDIM];

// ---------------- ptx helpers ----------------
__device__ __forceinline__ uint32_t smem_u32(const void* p) {
    uint32_t a;
    asm("{ .reg .u64 t; cvta.to.shared.u64 t, %1; cvt.u32.u64 %0, t; }"
        : "=r"(a) : "l"(p));
    return a;
}
__device__ __forceinline__ void cp16(uint32_t dst, const void* src) {
    asm volatile("cp.async.cg.shared.global [%0], [%1], 16;"
                 :: "r"(dst), "l"(src) : "memory");
}
__device__ __forceinline__ void cp_commit() {
    asm volatile("cp.async.commit_group;" ::: "memory");
}
template <int N>
__device__ __forceinline__ void cp_wait() {
    asm volatile("cp.async.wait_group %0;" :: "n"(N) : "memory");
}
__device__ __forceinline__ void ldsm4(uint32_t& r0, uint32_t& r1, uint32_t& r2,
                                      uint32_t& r3, uint32_t a) {
    asm volatile("ldmatrix.sync.aligned.m8n8.x4.shared.b16 {%0,%1,%2,%3}, [%4];"
                 : "=r"(r0), "=r"(r1), "=r"(r2), "=r"(r3) : "r"(a));
}
__device__ __forceinline__ void ldsm2(uint32_t& r0, uint32_t& r1, uint32_t a) {
    asm volatile("ldmatrix.sync.aligned.m8n8.x2.shared.b16 {%0,%1}, [%2];"
                 : "=r"(r0), "=r"(r1) : "r"(a));
}
__device__ __forceinline__ void mma_f16(float& d0, float& d1, float& d2, float& d3,
                                        uint32_t a0, uint32_t a1, uint32_t a2,
                                        uint32_t a3, uint32_t b0, uint32_t b1) {
    asm volatile(
        "mma.sync.aligned.m16n8k16.row.col.f32.f16.f16.f32 "
        "{%0,%1,%2,%3}, {%4,%5,%6,%7}, {%8,%9}, {%0,%1,%2,%3};"
        : "+f"(d0), "+f"(d1), "+f"(d2), "+f"(d3)
        : "r"(a0), "r"(a1), "r"(a2), "r"(a3), "r"(b0), "r"(b1));
}
__device__ __forceinline__ uint32_t pack_h2(half a, half b) {
    __half2 t = __halves2half2(a, b);
    return *reinterpret_cast<uint32_t*>(&t);
}

// ---------------- reset ----------------
__global__ void reset_kernel() {
    if (threadIdx.x < NEXP) g_cnt[threadIdx.x] = 0;
}

// ---------------- fused weight conversion (hi only, x64 scaled) --------------
// seg: 0 wq, 1 wk, 2 wv, 3 wo, 4 w2, 5 w1->w13(first half), 6 w3->w13(2nd half)
__global__ void conv_all_kernel(const float4* __restrict__ wq,
                                const float4* __restrict__ wk,
                                const float4* __restrict__ wv,
                                const float4* __restrict__ wo,
                                const float4* __restrict__ w1,
                                const float4* __restrict__ w2,
                                const float4* __restrict__ w3) {
    int seg = blockIdx.y;
    const float4* src;
    uint2* hi;
    int n4;
    bool strided = false;
    int off4 = 0;
    switch (seg) {
        case 0: src = wq; hi = (uint2*)g_wqkvh; n4 = 262144; break;
        case 1: src = wk; hi = (uint2*)(g_wqkvh + 1048576); n4 = 131072; break;
        case 2: src = wv; hi = (uint2*)(g_wqkvh + 1572864); n4 = 131072; break;
        case 3: src = wo; hi = (uint2*)g_woh; n4 = 262144; break;
        case 4: src = w2; hi = (uint2*)g_w2h; n4 = 7340032; break;
        case 5: src = w1; hi = (uint2*)g_w13h; n4 = 7340032;
                strided = true; off4 = 0; break;
        default: src = w3; hi = (uint2*)g_w13h; n4 = 7340032;
                strided = true; off4 = 917504; break;
    }
    for (int i = blockIdx.x * blockDim.x + threadIdx.x; i < n4;
         i += gridDim.x * blockDim.x) {
        float4 v = src[i];
        half h0 = __float2half_rn(v.x * OPSCALE);
        half h1 = __float2half_rn(v.y * OPSCALE);
        half h2 = __float2half_rn(v.z * OPSCALE);
        half h3 = __float2half_rn(v.w * OPSCALE);
        int d = i;
        if (strided) {
            int e = i / 917504;
            int rem = i - e * 917504;
            d = e * 1835008 + off4 + rem;
        }
        hi[d] = make_uint2(pack_h2(h0, h1), pack_h2(h2, h3));
    }
}

// ---------------- rmsnorm (fp32 + fp16 hi/lo out, x64) ----------------
__global__ void rmsnorm_kernel(const float* __restrict__ x,
                               const float* __restrict__ w,
                               float* __restrict__ o,
                               half* __restrict__ oh, half* __restrict__ ol) {
    int row = blockIdx.x;
    const float* xr = x + (size_t)row * H_DIM;
    float s = 0.f;
    for (int i = threadIdx.x; i < H_DIM; i += 256) {
        float v = xr[i];
        s += v * v;
    }
    __shared__ float red[8];
    int lane = threadIdx.x & 31, wid = threadIdx.x >> 5;
    #pragma unroll
    for (int off = 16; off; off >>= 1) s += __shfl_xor_sync(0xffffffffu, s, off);
    if (lane == 0) red[wid] = s;
    __syncthreads();
    if (wid == 0) {
        float t = (lane < 8) ? red[lane] : 0.f;
        #pragma unroll
        for (int off = 4; off; off >>= 1) t += __shfl_xor_sync(0xffffffffu, t, off);
        if (lane == 0) red[0] = t;
    }
    __syncthreads();
    float inv = rsqrtf(red[0] * (1.f / H_DIM) + 1e-6f);
    for (int i = threadIdx.x; i < H_DIM; i += 256) {
        float val = w[i] * xr[i] * inv;
        size_t off = (size_t)row * H_DIM + i;
        o[off] = val;
        float vs = val * OPSCALE;
        half h = __float2half_rn(vs);
        oh[off] = h;
        ol[off] = __float2half_rn(vs - __half2float(h));
    }
}

// ---------------- tensor-core NT GEMM via mma.sync (fp16, 1 or 2 A-terms) ----
// MODE 0: fp32 store   MODE 1: +resid dual fp32 store
// MODE 2: gathered A rows, fp16(x64) store   MODE 3: weighted atomic scatter
#define TILE_OFF 1024u

template <int MODE, int NTERM>
__global__ void __launch_bounds__(256, 2) tgemm(
    const half* __restrict__ Ah, const half* __restrict__ Al,
    const half* __restrict__ Bhb,
    float* __restrict__ Cb, int M, int N, int K,
    const float* __restrict__ resid, float* __restrict__ out2,
    float* __restrict__ finalout, half* __restrict__ Chb) {
    const uint32_t STG = (NTERM + 1) * 10240u;
    int z = blockIdx.z;
    int cnt = M;
    const half* Bh = Bhb;
    half* Ch = Chb;
    if (MODE == 2) {
        cnt = g_cnt[z];
        if ((int)blockIdx.y * 128 >= cnt) return;
        Bh = Bhb + (size_t)z * I2 * H_DIM;
        Ch = Chb + (size_t)z * S_LEN * I2;
    }
    if (MODE == 3) {
        cnt = g_cnt[z];
        if ((int)blockIdx.y * 128 >= cnt) return;
        Ah = Ah + (size_t)z * S_LEN * IDIM;
        Bh = Bhb + (size_t)z * H_DIM * IDIM;
    }

    extern __shared__ char smem[];
    uint32_t sb = smem_u32(smem);
    int* sidx = (int*)smem;
    float* swgt = (float*)(smem + 512);
    uint32_t tb = sb + TILE_OFF;

    int tid = threadIdx.x;
    int lane = tid & 31, wid = tid >> 5;
    int wr = wid >> 2, wc = wid & 3;
    int m0 = blockIdx.y * 128, n0 = blockIdx.x * 128;

    if (MODE == 2 || MODE == 3) {
        if (tid < 128) {
            int m = m0 + tid;
            sidx[tid] = (m < cnt) ? g_tok[z * S_LEN + m] : 0;
            swgt[tid] = (m < cnt) ? g_twgt[z * S_LEN + m] : 0.f;
        }
        __syncthreads();
    }

    int crow = tid >> 2;
    int cch = tid & 3;
    int arow0, arow1;
    if (MODE == 2) {
        arow0 = sidx[crow];
        arow1 = sidx[crow + 64];
    } else {
        arow0 = m0 + crow;
        arow1 = m0 + crow + 64;
    }
    const half* pAh0 = Ah + (size_t)arow0 * K + cch * 8;
    const half* pAh1 = Ah + (size_t)arow1 * K + cch * 8;
    const half* pAl0 = (NTERM == 2) ? (Al + (size_t)arow0 * K + cch * 8) : nullptr;
    const half* pAl1 = (NTERM == 2) ? (Al + (size_t)arow1 * K + cch * 8) : nullptr;
    const half* pBh0 = Bh + (size_t)(n0 + crow) * K + cch * 8;
    const half* pBh1 = Bh + (size_t)(n0 + crow + 64) * K + cch * 8;
    uint32_t d0 = (uint32_t)crow * 80u + (uint32_t)cch * 16u;
    uint32_t d1 = d0 + 64u * 80u;
    const uint32_t bOff = (uint32_t)NTERM * 10240u;

    float acc[4][4][4];
    #pragma unroll
    for (int a = 0; a < 4; a++)
        #pragma unroll
        for (int b = 0; b < 4; b++)
            #pragma unroll
            for (int c = 0; c < 4; c++) acc[a][b][c] = 0.f;

    int nst = K / 32;

    {
        uint32_t st = tb;
        cp16(st + d0, pAh0);
        cp16(st + d1, pAh1);
        if (NTERM == 2) {
            cp16(st + 10240u + d0, pAl0);
            cp16(st + 10240u + d1, pAl1);
        }
        cp16(st + bOff + d0, pBh0);
        cp16(st + bOff + d1, pBh1);
        cp_commit();
    }

    for (int s = 0; s < nst; s++) {
        if (s + 1 < nst) {
            uint32_t st = tb + (uint32_t)((s + 1) & 1) * STG;
            size_t ko = (size_t)(s + 1) * 32;
            cp16(st + d0, pAh0 + ko);
            cp16(st + d1, pAh1 + ko);
            if (NTERM == 2) {
                cp16(st + 10240u + d0, pAl0 + ko);
                cp16(st + 10240u + d1, pAl1 + ko);
            }
            cp16(st + bOff + d0, pBh0 + ko);
            cp16(st + bOff + d1, pBh1 + ko);
            cp_commit();
            cp_wait<1>();
        } else {
            cp_wait<0>();
        }
        __syncthreads();

        uint32_t st = tb + (uint32_t)(s & 1) * STG;
        #pragma unroll
        for (int kk = 0; kk < 2; kk++) {
            uint32_t bh[4][2];
            uint32_t bbase = st + bOff +
                             (uint32_t)(wc * 32 + (lane & 7)) * 80u +
                             (uint32_t)(kk * 32 + ((lane >> 3) & 1) * 16);
            #pragma unroll
            for (int nf = 0; nf < 4; nf++)
                ldsm2(bh[nf][0], bh[nf][1], bbase + nf * 8 * 80u);
            uint32_t abase = st + (uint32_t)(wr * 64 + (lane & 15)) * 80u +
                             (uint32_t)(kk * 32 + (lane >> 4) * 16);
            #pragma unroll
            for (int mf = 0; mf < 4; mf++) {
                uint32_t ah[4];
                ldsm4(ah[0], ah[1], ah[2], ah[3], abase + mf * 16 * 80u);
                #pragma unroll
                for (int nf = 0; nf < 4; nf++)
                    mma_f16(acc[mf][nf][0], acc[mf][nf][1], acc[mf][nf][2],
                            acc[mf][nf][3], ah[0], ah[1], ah[2], ah[3],
                            bh[nf][0], bh[nf][1]);
                if (NTERM == 2) {
                    uint32_t al[4];
                    ldsm4(al[0], al[1], al[2], al[3],
                          abase + mf * 16 * 80u + 10240u);
                    #pragma unroll
                    for (int nf = 0; nf < 4; nf++)
                        mma_f16(acc[mf][nf][0], acc[mf][nf][1], acc[mf][nf][2],
                                acc[mf][nf][3], al[0], al[1], al[2], al[3],
                                bh[nf][0], bh[nf][1]);
                }
            }
        }
        __syncthreads();
    }

    // epilogue (accumulators carry x4096 scale)
    int g = lane >> 2, cpr = (lane & 3) * 2;
    #pragma unroll
    for (int mf = 0; mf < 4; mf++) {
        int r0g = wr * 64 + mf * 16 + g;
        int m_lo = m0 + r0g, m_hi = m_lo + 8;
        #pragma unroll
        for (int nf = 0; nf < 4; nf++) {
            int n = n0 + wc * 32 + nf * 8 + cpr;
            float2 v01 = make_float2(acc[mf][nf][0] * INVACC,
                                     acc[mf][nf][1] * INVACC);
            float2 v23 = make_float2(acc[mf][nf][2] * INVACC,
                                     acc[mf][nf][3] * INVACC);
            if (MODE == 0) {
                *(float2*)(Cb + (size_t)m_lo * N + n) = v01;
                *(float2*)(Cb + (size_t)m_hi * N + n) = v23;
            } else if (MODE == 1) {
                size_t o_lo = (size_t)m_lo * N + n;
                size_t o_hi = (size_t)m_hi * N + n;
                float2 r0 = *(const float2*)(resid + o_lo);
                float2 r1 = *(const float2*)(resid + o_hi);
                v01.x += r0.x; v01.y += r0.y;
                v23.x += r1.x; v23.y += r1.y;
                *(float2*)(Cb + o_lo) = v01;
                *(float2*)(out2 + o_lo) = v01;
                *(float2*)(Cb + o_hi) = v23;
                *(float2*)(out2 + o_hi) = v23;
            } else if (MODE == 2) {
                if (m_lo < cnt) {
                    *(uint32_t*)(Ch + (size_t)m_lo * N + n) =
                        pack_h2(__float2half_rn(v01.x * OPSCALE),
                                __float2half_rn(v01.y * OPSCALE));
                }
                if (m_hi < cnt) {
                    *(uint32_t*)(Ch + (size_t)m_hi * N + n) =
                        pack_h2(__float2half_rn(v23.x * OPSCALE),
                                __float2half_rn(v23.y * OPSCALE));
                }
            } else {
                if (m_lo < cnt) {
                    float w = swgt[r0g];
                    float* dst = finalout + (size_t)sidx[r0g] * N + n;
                    atomicAdd(dst, w * v01.x);
                    atomicAdd(dst + 1, w * v01.y);
                }
                if (m_hi < cnt) {
                    float w = swgt[r0g + 8];
                    float* dst = finalout + (size_t)sidx[r0g + 8] * N + n;
                    atomicAdd(dst, w * v23.x);
                    atomicAdd(dst + 1, w * v23.y);
                }
            }
        }
    }
}

#define TG_SMEM2 (int)(TILE_OFF + 2 * 3 * 10240)
#define TG_SMEM1 (int)(TILE_OFF + 2 * 2 * 10240)

// ---------------- RoPE (packed qkv, in place) ----------------
__global__ void rope_kernel(float* __restrict__ qkv) {
    int s = blockIdx.x;
    int h = blockIdx.y * 8 + threadIdx.y;
    int d = threadIdx.x;
    float inv_freq = powf(1000000.0f, -(float)(2 * d) / 64.0f);
    float ang = (float)s * inv_freq;
    float sn, c;
    sincosf(ang, &sn, &c);
    float* base = (h < NHEAD)
                      ? (qkv + (size_t)s * QKV_LD + h * HDIM)
                      : (qkv + (size_t)s * QKV_LD + 1024 + (h - NHEAD) * HDIM);
    float x1 = base[d], x2 = base[d + 32];
    base[d]      = x1 * c - x2 * sn;
    base[d + 32] = x2 * c + x1 * sn;
}

// ---------------- flash attention (causal, GQA), fp16(x64) hi/lo out ---------
#define ALD 68
__global__ void attn_kernel(const float* __restrict__ qkv,
                            half* __restrict__ ctxh, half* __restrict__ ctxl) {
    extern __shared__ float sm[];
    float* Qs = sm;
    float* Ks = Qs + 64 * ALD;
    float* Vs = Ks + 64 * ALD;
    float* Ps = Vs + 64 * ALD;

    int qt = blockIdx.x, h = blockIdx.y;
    int kvh = h >> 1;
    int tid = threadIdx.x;
    int r = tid >> 2;
    int cg = tid & 3;
    int d0 = cg * 16;

    for (int i = tid; i < 64 * 16; i += 256) {
        int rr = i >> 4, dd = (i & 15) * 4;
        float4 v = *(const float4*)(qkv + (size_t)(qt * 64 + rr) * QKV_LD +
                                    h * HDIM + dd);
        v.x *= 0.125f; v.y *= 0.125f; v.z *= 0.125f; v.w *= 0.125f;
        *(float4*)&Qs[rr * ALD + dd] = v;
    }

    float m = -1e30f, l = 0.f;
    float o[16];
    #pragma unroll
    for (int j = 0; j < 16; j++) o[j] = 0.f;
    int qrow_g = qt * 64 + r;

    for (int kt = 0; kt <= qt; kt++) {
        for (int i = tid; i < 64 * 16; i += 256) {
            int rr = i >> 4, dd = (i & 15) * 4;
            size_t off = (size_t)(kt * 64 + rr) * QKV_LD + 1024 + kvh * HDIM + dd;
            *(float4*)&Ks[rr * ALD + dd] = *(const float4*)(qkv + off);
            *(float4*)&Vs[rr * ALD + dd] = *(const float4*)(qkv + off + 512);
        }
        __syncthreads();

        float sc[16];
        #pragma unroll
        for (int j = 0; j < 16; j++) sc[j] = 0.f;
        for (int kk = 0; kk < 64; kk += 4) {
            float4 qv = *(const float4*)&Qs[r * ALD + kk];
            #pragma unroll
            for (int j = 0; j < 16; j++) {
                float4 kv = *(const float4*)&Ks[(d0 + j) * ALD + kk];
                sc[j] += qv.x * kv.x + qv.y * kv.y + qv.z * kv.z + qv.w * kv.w;
            }
        }
        float tmax = -1e30f;
        #pragma unroll
        for (int j = 0; j < 16; j++) {
            int cglob = kt * 64 + d0 + j;
            if (cglob > qrow_g) sc[j] = -1e30f;
            tmax = fmaxf(tmax, sc[j]);
        }
        tmax = fmaxf(tmax, __shfl_xor_sync(0xffffffffu, tmax, 1));
        tmax = fmaxf(tmax, __shfl_xor_sync(0xffffffffu, tmax, 2));
        float mnew = fmaxf(m, tmax);
        float alpha = __expf(m - mnew);
        float lsum = 0.f;
        #pragma unroll
        for (int j = 0; j < 16; j++) {
            float p = __expf(sc[j] - mnew);
            Ps[r * ALD + d0 + j] = p;
            lsum += p;
        }
        lsum += __shfl_xor_sync(0xffffffffu, lsum, 1);
        lsum += __shfl_xor_sync(0xffffffffu, lsum, 2);
        l = l * alpha + lsum;
        m = mnew;
        #pragma unroll
        for (int j = 0; j < 16; j++) o[j] *= alpha;
        __syncthreads();

        for (int c = 0; c < 64; c++) {
            float p = Ps[r * ALD + c];
            #pragma unroll
            for (int jq = 0; jq < 4; jq++) {
                float4 vv = *(const float4*)&Vs[c * ALD + d0 + jq * 4];
                o[jq * 4 + 0] += p * vv.x;
                o[jq * 4 + 1] += p * vv.y;
                o[jq * 4 + 2] += p * vv.z;
                o[jq * 4 + 3] += p * vv.w;
            }
        }
        __syncthreads();
    }

    float invl = 1.f / l;
    size_t ob = (size_t)qrow_g * H_DIM + h * HDIM + d0;
    #pragma unroll
    for (int j = 0; j < 16; j++) {
        float vs = o[j] * invl * OPSCALE;
        half hh = __float2half_rn(vs);
        ctxh[ob + j] = hh;
        ctxl[ob + j] = __float2half_rn(vs - __half2float(hh));
    }
}

// ---------------- router ----------------
__global__ void router_kernel(const float* __restrict__ xn,
                              const float* __restrict__ gw) {
    int t = blockIdx.x;
    int wid = threadIdx.x >> 5, lane = threadIdx.x & 31;
    __shared__ float logit[NEXP];
    const float* xr = xn + (size_t)t * H_DIM;
    const float* gr = gw + (size_t)wid * H_DIM;
    float s = 0.f;
    for (int i = lane; i < H_DIM; i += 32) s += xr[i] * gr[i];
    #pragma unroll
    for (int off = 16; off; off >>= 1) s += __shfl_xor_sync(0xffffffffu, s, off);
    if (lane == 0) logit[wid] = s;
    __syncthreads();
    if (threadIdx.x == 0) {
        float mx = -1e30f;
        for (int e = 0; e < NEXP; e++) mx = fmaxf(mx, logit[e]);
        float rw[NEXP], sum = 0.f;
        for (int e = 0; e < NEXP; e++) { rw[e] = expf(logit[e] - mx); sum += rw[e]; }
        float invs = 1.f / sum;
        for (int e = 0; e < NEXP; e++) rw[e] *= invs;
        int ba = 0, bb = 1;
        float best = -1.f;
        for (int a = 0; a < NEXP; a++)
            for (int b = a + 1; b < NEXP; b++) {
                float vv = rw[a] + rw[b];
                if (vv > best) { best = vv; ba = a; bb = b; }
            }
        float wa = rw[ba], wb = rw[bb];
        float inv = 1.f / (wa + wb);
        int sa = atomicAdd(&g_cnt[ba], 1);
        g_tok[ba * S_LEN + sa] = t; g_twgt[ba * S_LEN + sa] = wa * inv;
        int sb = atomicAdd(&g_cnt[bb], 1);
        g_tok[bb * S_LEN + sb] = t; g_twgt[bb * S_LEN + sb] = wb * inv;
    }
}

// ---------------- silu(h1)*h3 from fused s13 (fp16 x64 in & out) -------------
__global__ void silu_mul_kernel() {
    int e = blockIdx.z;
    int row = blockIdx.y;
    if (row >= g_cnt[e]) return;
    int i = blockIdx.x * 256 + threadIdx.x;
    size_t base = ((size_t)e * S_LEN + row) * I2;
    float a = __half2float(g_s13h[base + i]) * (1.0f / OPSCALE);
    float b = __half2float(g_s13h[base + i + IDIM]) * (1.0f / OPSCALE);
    float gv = a * (1.f / (1.f + expf(-a))) * b;
    size_t o = ((size_t)e * S_LEN + row) * IDIM + i;
    g_s1h[o] = __float2half_rn(gv * OPSCALE);
}

// ---------------- launch ----------------
static void* symaddr(const void* sym) {
    void* p = nullptr;
    cudaGetSymbolAddress(&p, sym);
    return p;
}

extern "C" void kernel_launch(void* const* d_in, const int* in_sizes, int n_in,
                              void* d_out, int out_size) {
    const float* hidden = (const float*)d_in[0];
    const float* ln1    = (const float*)d_in[1];
    const float* ln2    = (const float*)d_in[2];
    const float* wq     = (const float*)d_in[3];
    const float* wk     = (const float*)d_in[4];
    const float* wv     = (const float*)d_in[5];
    const float* wo     = (const float*)d_in[6];
    const float* gate   = (const float*)d_in[7];
    const float* w1     = (const float*)d_in[8];
    const float* w2     = (const float*)d_in[9];
    const float* w3     = (const float*)d_in[10];
    float* out = (float*)d_out;

    float* xn   = (float*)symaddr(g_xn);
    half* xnh   = (half*)symaddr(g_xnh);
    half* xnl   = (half*)symaddr(g_xnl);
    float* qkv  = (float*)symaddr(g_qkv);
    half* ctxh  = (half*)symaddr(g_ctxh);
    half* ctxl  = (half*)symaddr(g_ctxl);
    float* hid  = (float*)symaddr(g_hid);
    half* s13h  = (half*)symaddr(g_s13h);
    half* s1h   = (half*)symaddr(g_s1h);
    half* wqkvh = (half*)symaddr(g_wqkvh);
    half* woh   = (half*)symaddr(g_woh);
    half* w13h  = (half*)symaddr(g_w13h);
    half* w2h   = (half*)symaddr(g_w2h);

    cudaFuncSetAttribute(tgemm<0, 2>, cudaFuncAttributeMaxDynamicSharedMemorySize,
                         TG_SMEM2);
    cudaFuncSetAttribute(tgemm<1, 2>, cudaFuncAttributeMaxDynamicSharedMemorySize,
                         TG_SMEM2);
    cudaFuncSetAttribute(tgemm<2, 1>, cudaFuncAttributeMaxDynamicSharedMemorySize,
                         TG_SMEM1);
    cudaFuncSetAttribute(tgemm<3, 1>, cudaFuncAttributeMaxDynamicSharedMemorySize,
                         TG_SMEM1);
    int attn_smem = 4 * 64 * ALD * (int)sizeof(float);
    cudaFuncSetAttribute(attn_kernel, cudaFuncAttributeMaxDynamicSharedMemorySize,
                         attn_smem);

    // 1: all weight conversions in one launch (hi only, x64)
    conv_all_kernel<<<dim3(2048, 7), 256>>>(
        (const float4*)wq, (const float4*)wk, (const float4*)wv,
        (const float4*)wo, (const float4*)w1, (const float4*)w2,
        (const float4*)w3);

    // 2: rmsnorm 1
    rmsnorm_kernel<<<S_LEN, 256>>>(hidden, ln1, xn, xnh, xnl);

    // 3: packed QKV projection (2-term)
    tgemm<0, 2><<<dim3(16, 16, 1), 256, TG_SMEM2>>>(
        xnh, xnl, wqkvh, qkv, S_LEN, QKV_LD, H_DIM,
        nullptr, nullptr, nullptr, nullptr);

    // 4: rope
    rope_kernel<<<dim3(S_LEN, 3), dim3(32, 8)>>>(qkv);

    // 5: attention
    attn_kernel<<<dim3(S_LEN / 64, NHEAD), 256, attn_smem>>>(qkv, ctxh, ctxl);

    // 6: wo projection + residual (2-term)
    tgemm<1, 2><<<dim3(8, 16, 1), 256, TG_SMEM2>>>(
        ctxh, ctxl, woh, hid, S_LEN, H_DIM, H_DIM,
        hidden, out, nullptr, nullptr);

    // 7: rmsnorm 2
    rmsnorm_kernel<<<S_LEN, 256>>>(hid, ln2, xn, xnh, xnl);

    // 8-9: router
    reset_kernel<<<1, 32>>>();
    router_kernel<<<S_LEN, 256>>>(xn, gate);

    // 10: fused w1|w3 GEMM (1-term), fp16 epilogue
    tgemm<2, 1><<<dim3(I2 / 128, S_LEN / 128, NEXP), 256, TG_SMEM1>>>(
        xnh, nullptr, w13h, nullptr, S_LEN, I2, H_DIM,
        nullptr, nullptr, nullptr, s13h);

    // 11: silu * mul
    silu_mul_kernel<<<dim3(IDIM / 256, S_LEN, NEXP), 256>>>();

    // 12: w2 GEMM (1-term) with weighted atomic scatter into out
    tgemm<3, 1><<<dim3(H_DIM / 128, S_LEN / 128, NEXP), 256, TG_SMEM1>>>(
        s1h, nullptr, w2h, nullptr, S_LEN, H_DIM, IDIM,
        nullptr, nullptr, out, nullptr);
}